// round 4
// baseline (speedup 1.0000x reference)
#include <cuda_runtime.h>
#include <cuda_bf16.h>
#include <math.h>
#include <stdint.h>

#define BB 32
#define TT 1024
#define JJ 256
#define DD 512
#define NCHUNK 8

// ---------------- scratch (device globals) ----------------------------------
__device__ float g_S[BB * TT * JJ];                    // raw S (32 MB)
__device__ __nv_bfloat16 g_Chi[BB * TT * DD];          // split of C*w3
__device__ __nv_bfloat16 g_Clo[BB * TT * DD];
__device__ __nv_bfloat16 g_Qhi[BB * JJ * DD];
__device__ __nv_bfloat16 g_Qlo[BB * JJ * DD];
__device__ __nv_bfloat16 g_Phi[BB * TT * JJ];
__device__ __nv_bfloat16 g_Plo[BB * TT * JJ];
__device__ float g_c1[BB * TT];
__device__ float g_q2[BB * JJ];
__device__ float g_mp[BB * 2 * TT];                    // row-max partials (per j-tile)
__device__ float g_pM[BB * NCHUNK * JJ];
__device__ float g_pZ[BB * NCHUNK * JJ];
__device__ float g_M[BB * JJ];
__device__ float g_invZ[BB * JJ];
__device__ float g_bt[BB * TT];
__device__ float g_hp[BB * NCHUNK * DD];
__device__ float g_h[BB * DD];

// ---------------- helpers ----------------------------------------------------
__device__ __forceinline__ uint32_t smem_u32(const void* p) {
    uint32_t a;
    asm("{ .reg .u64 t; cvta.to.shared.u64 t, %1; cvt.u32.u64 %0, t; }" : "=r"(a) : "l"(p));
    return a;
}
__device__ __forceinline__ void cpa16(uint32_t dst, const void* src) {
    asm volatile("cp.async.cg.shared.global [%0], [%1], 16;" :: "r"(dst), "l"(src));
}
__device__ __forceinline__ void cpa_commit() {
    asm volatile("cp.async.commit_group;" ::: "memory");
}
template <int N>
__device__ __forceinline__ void cpa_wait() {
    asm volatile("cp.async.wait_group %0;" :: "n"(N) : "memory");
}
__device__ __forceinline__ void ldmx4(uint32_t* r, uint32_t a) {
    asm volatile("ldmatrix.sync.aligned.m8n8.x4.shared.b16 {%0,%1,%2,%3}, [%4];"
                 : "=r"(r[0]), "=r"(r[1]), "=r"(r[2]), "=r"(r[3]) : "r"(a));
}
__device__ __forceinline__ void ldmx4t(uint32_t* r, uint32_t a) {
    asm volatile("ldmatrix.sync.aligned.m8n8.x4.trans.shared.b16 {%0,%1,%2,%3}, [%4];"
                 : "=r"(r[0]), "=r"(r[1]), "=r"(r[2]), "=r"(r[3]) : "r"(a));
}
__device__ __forceinline__ void mma_bf16(float* c, const uint32_t* a, uint32_t b0, uint32_t b1) {
    asm volatile(
        "mma.sync.aligned.m16n8k16.row.col.f32.bf16.bf16.f32 "
        "{%0,%1,%2,%3}, {%4,%5,%6,%7}, {%8,%9}, {%0,%1,%2,%3};"
        : "+f"(c[0]), "+f"(c[1]), "+f"(c[2]), "+f"(c[3])
        : "r"(a[0]), "r"(a[1]), "r"(a[2]), "r"(a[3]), "r"(b0), "r"(b1));
}
__device__ __forceinline__ void split2(float v, __nv_bfloat16& h, __nv_bfloat16& l) {
    h = __float2bfloat16(v);
    l = __float2bfloat16(v - __bfloat162float(h));
}
__device__ __forceinline__ void conv8(const float* v, uint4* hi, uint4* lo) {
    __align__(16) __nv_bfloat16 h8[8], l8[8];
#pragma unroll
    for (int e = 0; e < 8; e++) split2(v[e], h8[e], l8[e]);
    *hi = *(uint4*)h8;
    *lo = *(uint4*)l8;
}

// ---------------- K0: row dot products --------------------------------------
__global__ __launch_bounds__(256) void k_rowdot(const float* __restrict__ X,
                                                const float* __restrict__ w,
                                                float* __restrict__ out, int nrows) {
    int warp = (blockIdx.x * 256 + threadIdx.x) >> 5;
    int lane = threadIdx.x & 31;
    if (warp >= nrows) return;
    const float* row = X + (size_t)warp * DD;
    float s = 0.f;
#pragma unroll
    for (int i = 0; i < DD / 32; i++)
        s += row[lane + i * 32] * __ldg(&w[lane + i * 32]);
#pragma unroll
    for (int o = 16; o > 0; o >>= 1) s += __shfl_down_sync(0xffffffffu, s, o);
    if (lane == 0) out[warp] = s;
}

// ---------------- conversion passes ------------------------------------------
__global__ __launch_bounds__(256) void k_convC(const float* __restrict__ C,
                                               const float* __restrict__ w3) {
    size_t f = (size_t)blockIdx.x * 256 + threadIdx.x;
    size_t base = f * 8;
    int d = (int)(base & (DD - 1));
    float4 v0 = *(const float4*)(C + base);
    float4 v1 = *(const float4*)(C + base + 4);
    float v[8] = {v0.x, v0.y, v0.z, v0.w, v1.x, v1.y, v1.z, v1.w};
#pragma unroll
    for (int e = 0; e < 8; e++) v[e] *= __ldg(&w3[d + e]);
    uint4 hi, lo; conv8(v, &hi, &lo);
    *(uint4*)(g_Chi + base) = hi;
    *(uint4*)(g_Clo + base) = lo;
}
__global__ __launch_bounds__(256) void k_convQ(const float* __restrict__ Q) {
    size_t f = (size_t)blockIdx.x * 256 + threadIdx.x;
    size_t base = f * 8;
    float4 v0 = *(const float4*)(Q + base);
    float4 v1 = *(const float4*)(Q + base + 4);
    float v[8] = {v0.x, v0.y, v0.z, v0.w, v1.x, v1.y, v1.z, v1.w};
    uint4 hi, lo; conv8(v, &hi, &lo);
    *(uint4*)(g_Qhi + base) = hi;
    *(uint4*)(g_Qlo + base) = lo;
}

// ---------------- S-GEMM: S[128t x 128j], fused rowmax + col partial stats ---
// Stage: Ahi/Alo 128x64 bf16 (16KB each), Bhi/Blo 128x64 (16KB each) = 64KB, x2.
#define SG_STAGE 65536
#define SG_AHI 0
#define SG_ALO 16384
#define SG_BHI 32768
#define SG_BLO 49152
__global__ __launch_bounds__(256) void k_s_mma() {
    extern __shared__ __align__(16) char dsm[];
    __shared__ float c1s[128], q2s[128];
    __shared__ float sRM[4][128];
    __shared__ float sCM[2][128], sCZ[2][128];

    const int tid = threadIdx.x, lane = tid & 31, wid = tid >> 5;
    const int b = blockIdx.z, tb = blockIdx.y, jt = blockIdx.x;
    const int t0 = tb * 128, j0 = jt * 128;

    if (tid < 128) {
        c1s[tid] = g_c1[b * TT + t0 + tid];
        q2s[tid] = g_q2[b * JJ + j0 + tid];
    }

    const uint32_t smb = smem_u32(dsm);
    // staging indices: A: row la (0..127), chunks lc..lc+3 ; B identical
    const int la = tid >> 1, lcb = (tid & 1) * 4;
    const uint32_t arow_off = la * 128 + ((la & 7) << 4) * 0; // (swizzle applied per chunk)
    const size_t aGrow = (size_t)(b * TT + t0 + la) * DD;
    const size_t bGrow = (size_t)(b * JJ + j0 + la) * DD;

    // preload stage 0
    {
        const __nv_bfloat16* ah = g_Chi + aGrow;
        const __nv_bfloat16* al = g_Clo + aGrow;
        const __nv_bfloat16* bh = g_Qhi + bGrow;
        const __nv_bfloat16* bl = g_Qlo + bGrow;
#pragma unroll
        for (int i = 0; i < 4; i++) {
            int c = lcb + i;
            uint32_t d = la * 128 + (((c ^ (la & 7)) & 7) << 4);
            cpa16(smb + SG_AHI + d, ah + c * 8);
            cpa16(smb + SG_ALO + d, al + c * 8);
            cpa16(smb + SG_BHI + d, bh + c * 8);
            cpa16(smb + SG_BLO + d, bl + c * 8);
        }
        cpa_commit();
    }

    const int wm = wid >> 2, wn = wid & 3;
    float acc[4][4][4];
#pragma unroll
    for (int i = 0; i < 4; i++)
#pragma unroll
        for (int j = 0; j < 4; j++)
#pragma unroll
            for (int e = 0; e < 4; e++) acc[i][j][e] = 0.f;

    const int lsw = lane & 7;
    const int arow = wm * 64 + (lane & 7) + ((lane >> 3) & 1) * 8;
    const int ack = lane >> 4;
    const int brow = wn * 32 + (lane & 7) + ((lane >> 4) & 1) * 8;
    const int bck = (lane >> 3) & 1;

#pragma unroll 1
    for (int kc = 0; kc < 8; kc++) {
        if (kc + 1 < 8) {
            uint32_t st = smb + ((kc + 1) & 1) * SG_STAGE;
            const __nv_bfloat16* ah = g_Chi + aGrow + (kc + 1) * 64;
            const __nv_bfloat16* al = g_Clo + aGrow + (kc + 1) * 64;
            const __nv_bfloat16* bh = g_Qhi + bGrow + (kc + 1) * 64;
            const __nv_bfloat16* bl = g_Qlo + bGrow + (kc + 1) * 64;
#pragma unroll
            for (int i = 0; i < 4; i++) {
                int c = lcb + i;
                uint32_t d = la * 128 + (((c ^ (la & 7)) & 7) << 4);
                cpa16(st + SG_AHI + d, ah + c * 8);
                cpa16(st + SG_ALO + d, al + c * 8);
                cpa16(st + SG_BHI + d, bh + c * 8);
                cpa16(st + SG_BLO + d, bl + c * 8);
            }
            cpa_commit();
            cpa_wait<1>();
        } else {
            cpa_wait<0>();
        }
        __syncthreads();
        const uint32_t sb = smb + (kc & 1) * SG_STAGE;
#pragma unroll
        for (int s = 0; s < 4; s++) {
            uint32_t Ah[4][4], Al[4][4], Bh[2][4], Bl[2][4];
            const int ca = s * 2 + ack;
            const int cb = s * 2 + bck;
#pragma unroll
            for (int mi = 0; mi < 4; mi++) {
                uint32_t ro = (arow + mi * 16) * 128 + ((ca ^ lsw) << 4);
                ldmx4(Ah[mi], sb + SG_AHI + ro);
                ldmx4(Al[mi], sb + SG_ALO + ro);
            }
#pragma unroll
            for (int n2 = 0; n2 < 2; n2++) {
                uint32_t ro = (brow + n2 * 16) * 128 + ((cb ^ lsw) << 4);
                ldmx4(Bh[n2], sb + SG_BHI + ro);
                ldmx4(Bl[n2], sb + SG_BLO + ro);
            }
#pragma unroll
            for (int mi = 0; mi < 4; mi++)
#pragma unroll
                for (int ni = 0; ni < 4; ni++) {
                    const uint32_t* bp = &Bh[ni >> 1][(ni & 1) * 2];
                    mma_bf16(acc[mi][ni], Ah[mi], bp[0], bp[1]);
                }
#pragma unroll
            for (int mi = 0; mi < 4; mi++)
#pragma unroll
                for (int ni = 0; ni < 4; ni++) {
                    const uint32_t* bp = &Bl[ni >> 1][(ni & 1) * 2];
                    mma_bf16(acc[mi][ni], Ah[mi], bp[0], bp[1]);
                }
#pragma unroll
            for (int mi = 0; mi < 4; mi++)
#pragma unroll
                for (int ni = 0; ni < 4; ni++) {
                    const uint32_t* bp = &Bh[ni >> 1][(ni & 1) * 2];
                    mma_bf16(acc[mi][ni], Al[mi], bp[0], bp[1]);
                }
        }
        __syncthreads();
    }

    // ---- epilogue: add biases, store S, fused row-max + column partial stats
    const int g = lane >> 2, tc = (lane & 3) * 2;
#pragma unroll
    for (int mi = 0; mi < 4; mi++) {
        const int tl = wm * 64 + mi * 16 + g;
        const float c1a = c1s[tl], c1b = c1s[tl + 8];
        float* row0 = &g_S[((size_t)(b * TT + t0 + tl)) * JJ + j0];
        float* row1 = row0 + (size_t)8 * JJ;
#pragma unroll
        for (int ni = 0; ni < 4; ni++) {
            const int jl = wn * 32 + ni * 8 + tc;
            const float q2a = q2s[jl], q2b = q2s[jl + 1];
            acc[mi][ni][0] += c1a + q2a;
            acc[mi][ni][1] += c1a + q2b;
            acc[mi][ni][2] += c1b + q2a;
            acc[mi][ni][3] += c1b + q2b;
            *(float2*)(row0 + jl) = make_float2(acc[mi][ni][0], acc[mi][ni][1]);
            *(float2*)(row1 + jl) = make_float2(acc[mi][ni][2], acc[mi][ni][3]);
        }
    }
    // row max (over this CTA's 128 j)
#pragma unroll
    for (int mi = 0; mi < 4; mi++) {
#pragma unroll
        for (int rr = 0; rr < 2; rr++) {
            float m = -1e30f;
#pragma unroll
            for (int ni = 0; ni < 4; ni++)
                m = fmaxf(m, fmaxf(acc[mi][ni][rr * 2], acc[mi][ni][rr * 2 + 1]));
            m = fmaxf(m, __shfl_xor_sync(0xffffffffu, m, 1));
            m = fmaxf(m, __shfl_xor_sync(0xffffffffu, m, 2));
            if ((lane & 3) == 0) sRM[wn][wm * 64 + mi * 16 + g + rr * 8] = m;
        }
    }
    // column stats (max & sum-exp over this CTA's 128 t)
#pragma unroll
    for (int ni = 0; ni < 4; ni++) {
#pragma unroll
        for (int cc = 0; cc < 2; cc++) {
            float m = -1e30f;
#pragma unroll
            for (int mi = 0; mi < 4; mi++)
                m = fmaxf(m, fmaxf(acc[mi][ni][cc], acc[mi][ni][2 + cc]));
            float z = 0.f;
#pragma unroll
            for (int mi = 0; mi < 4; mi++)
                z += __expf(acc[mi][ni][cc] - m) + __expf(acc[mi][ni][2 + cc] - m);
#pragma unroll
            for (int o = 4; o < 32; o <<= 1) {
                float Mo = __shfl_xor_sync(0xffffffffu, m, o);
                float Zo = __shfl_xor_sync(0xffffffffu, z, o);
                float nm = fmaxf(m, Mo);
                z = z * __expf(m - nm) + Zo * __expf(Mo - nm);
                m = nm;
            }
            if (g == 0) {
                sCM[wm][wn * 32 + ni * 8 + tc + cc] = m;
                sCZ[wm][wn * 32 + ni * 8 + tc + cc] = z;
            }
        }
    }
    __syncthreads();
    if (tid < 128) {
        float m = fmaxf(fmaxf(sRM[0][tid], sRM[1][tid]), fmaxf(sRM[2][tid], sRM[3][tid]));
        g_mp[((size_t)(b * 2 + jt)) * TT + t0 + tid] = m;
        float M0 = sCM[0][tid], M1 = sCM[1][tid];
        float nm = fmaxf(M0, M1);
        float Z = sCZ[0][tid] * __expf(M0 - nm) + sCZ[1][tid] * __expf(M1 - nm);
        g_pM[(b * NCHUNK + tb) * JJ + j0 + tid] = nm;
        g_pZ[(b * NCHUNK + tb) * JJ + j0 + tid] = Z;
    }
}

// ---------------- combine / bt / h -------------------------------------------
__global__ __launch_bounds__(256) void k_colcombine() {
    int b = blockIdx.x, j = threadIdx.x;
    float M = -1e30f;
#pragma unroll
    for (int c = 0; c < NCHUNK; c++) M = fmaxf(M, g_pM[(b * NCHUNK + c) * JJ + j]);
    float Z = 0.f;
#pragma unroll
    for (int c = 0; c < NCHUNK; c++)
        Z += g_pZ[(b * NCHUNK + c) * JJ + j] * __expf(g_pM[(b * NCHUNK + c) * JJ + j] - M);
    g_M[b * JJ + j] = M;
    g_invZ[b * JJ + j] = 1.0f / Z;
}
__global__ __launch_bounds__(256) void k_bt() {
    __shared__ float red[256];
    int b = blockIdx.x, tid = threadIdx.x;
    float mv[4];
#pragma unroll
    for (int i = 0; i < 4; i++) {
        int t = tid + i * 256;
        mv[i] = fmaxf(g_mp[((size_t)(b * 2)) * TT + t], g_mp[((size_t)(b * 2 + 1)) * TT + t]);
    }
    float mx = fmaxf(fmaxf(mv[0], mv[1]), fmaxf(mv[2], mv[3]));
    red[tid] = mx;
    __syncthreads();
    for (int s = 128; s > 0; s >>= 1) {
        if (tid < s) red[tid] = fmaxf(red[tid], red[tid + s]);
        __syncthreads();
    }
    float bmax = red[0];
    __syncthreads();
    float e[4], ssum = 0.f;
#pragma unroll
    for (int i = 0; i < 4; i++) { e[i] = __expf(mv[i] - bmax); ssum += e[i]; }
    red[tid] = ssum;
    __syncthreads();
    for (int s = 128; s > 0; s >>= 1) {
        if (tid < s) red[tid] += red[tid + s];
        __syncthreads();
    }
    float inv = 1.0f / red[0];
#pragma unroll
    for (int i = 0; i < 4; i++) g_bt[b * TT + tid + i * 256] = e[i] * inv;
}
__global__ __launch_bounds__(256) void k_hpart(const float* __restrict__ C) {
    __shared__ float bts[TT / NCHUNK];
    int b = blockIdx.y, chunk = blockIdx.x;
    int tid = threadIdx.x;
    if (tid < TT / NCHUNK) bts[tid] = g_bt[b * TT + chunk * (TT / NCHUNK) + tid];
    __syncthreads();
    float a0 = 0.f, a1 = 0.f;
    for (int tt = 0; tt < TT / NCHUNK; tt++) {
        int t = chunk * (TT / NCHUNK) + tt;
        const float* cr = C + ((size_t)(b * TT + t)) * DD;
        a0 = fmaf(bts[tt], cr[tid], a0);
        a1 = fmaf(bts[tt], cr[tid + 256], a1);
    }
    g_hp[(b * NCHUNK + chunk) * DD + tid] = a0;
    g_hp[(b * NCHUNK + chunk) * DD + tid + 256] = a1;
}
__global__ __launch_bounds__(512) void k_hcombine() {
    int b = blockIdx.x, d = threadIdx.x;
    float s = 0.f;
#pragma unroll
    for (int c = 0; c < NCHUNK; c++) s += g_hp[(b * NCHUNK + c) * DD + d];
    g_h[b * DD + d] = s;
}

// ---------------- P split: P = exp(S-M)*invZ -> Phi/Plo ----------------------
__global__ __launch_bounds__(256) void k_psplit() {
    size_t f = (size_t)blockIdx.x * 256 + threadIdx.x;
    size_t base = f * 8;
    int j = (int)(base & (JJ - 1));
    int row = (int)(base >> 8);
    int b = row >> 10;
    float4 v0 = *(const float4*)(g_S + base);
    float4 v1 = *(const float4*)(g_S + base + 4);
    float4 M0 = *(const float4*)(g_M + b * JJ + j);
    float4 M1 = *(const float4*)(g_M + b * JJ + j + 4);
    float4 z0 = *(const float4*)(g_invZ + b * JJ + j);
    float4 z1 = *(const float4*)(g_invZ + b * JJ + j + 4);
    float v[8];
    v[0] = __expf(v0.x - M0.x) * z0.x;
    v[1] = __expf(v0.y - M0.y) * z0.y;
    v[2] = __expf(v0.z - M0.z) * z0.z;
    v[3] = __expf(v0.w - M0.w) * z0.w;
    v[4] = __expf(v1.x - M1.x) * z1.x;
    v[5] = __expf(v1.y - M1.y) * z1.y;
    v[6] = __expf(v1.z - M1.z) * z1.z;
    v[7] = __expf(v1.w - M1.w) * z1.w;
    uint4 hi, lo; conv8(v, &hi, &lo);
    *(uint4*)(g_Phi + base) = hi;
    *(uint4*)(g_Plo + base) = lo;
}

// ---------------- U-GEMM: U[128t x 128d] = P @ Q, full G epilogue ------------
// Stage: Ahi/Alo 128x64 (16KB each), Bhi/Blo 64 j-rows x 128 d (16KB each).
#define UG_STAGE 65536
#define UG_AHI 0
#define UG_ALO 16384
#define UG_BHI 32768
#define UG_BLO 49152
__global__ __launch_bounds__(256) void k_u_mma(const float* __restrict__ C,
                                               float* __restrict__ G) {
    extern __shared__ __align__(16) char dsm[];
    __shared__ float hs[128];

    const int tid = threadIdx.x, lane = tid & 31, wid = tid >> 5;
    const int b = blockIdx.z, t0 = blockIdx.y * 128, d0 = blockIdx.x * 128;

    if (tid < 128) hs[tid] = g_h[b * DD + d0 + tid];

    const uint32_t smb = smem_u32(dsm);
    const int la = tid >> 1, lcbA = (tid & 1) * 4;        // A staging
    const int lb = tid >> 2, lcbB = (tid & 3) * 4;        // B staging (64 rows x 16 chunks)
    const size_t aGrow = (size_t)(b * TT + t0 + la) * JJ;

    // preload stage 0
    {
        const __nv_bfloat16* ah = g_Phi + aGrow;
        const __nv_bfloat16* al = g_Plo + aGrow;
        const __nv_bfloat16* bh = g_Qhi + (size_t)(b * JJ + lb) * DD + d0;
        const __nv_bfloat16* bl = g_Qlo + (size_t)(b * JJ + lb) * DD + d0;
#pragma unroll
        for (int i = 0; i < 4; i++) {
            int c = lcbA + i;
            uint32_t d = la * 128 + (((c ^ (la & 7)) & 7) << 4);
            cpa16(smb + UG_AHI + d, ah + c * 8);
            cpa16(smb + UG_ALO + d, al + c * 8);
            int cb = lcbB + i;
            uint32_t db = lb * 256 + (((((cb ^ (lb & 7)) & 7) | (cb & 8))) << 4);
            cpa16(smb + UG_BHI + db, bh + cb * 8);
            cpa16(smb + UG_BLO + db, bl + cb * 8);
        }
        cpa_commit();
    }

    const int wm = wid >> 2, wn = wid & 3;
    float acc[4][4][4];
#pragma unroll
    for (int i = 0; i < 4; i++)
#pragma unroll
        for (int j = 0; j < 4; j++)
#pragma unroll
            for (int e = 0; e < 4; e++) acc[i][j][e] = 0.f;

    const int lsw = lane & 7;
    const int arow = wm * 64 + (lane & 7) + ((lane >> 3) & 1) * 8;
    const int ack = lane >> 4;
    const int bkrow = (lane & 7) + ((lane >> 3) & 1) * 8;
    const int bcn = wn * 4 + (lane >> 4);

#pragma unroll 1
    for (int kc = 0; kc < 4; kc++) {
        if (kc + 1 < 4) {
            uint32_t st = smb + ((kc + 1) & 1) * UG_STAGE;
            const __nv_bfloat16* ah = g_Phi + aGrow + (kc + 1) * 64;
            const __nv_bfloat16* al = g_Plo + aGrow + (kc + 1) * 64;
            const __nv_bfloat16* bh = g_Qhi + (size_t)(b * JJ + (kc + 1) * 64 + lb) * DD + d0;
            const __nv_bfloat16* bl = g_Qlo + (size_t)(b * JJ + (kc + 1) * 64 + lb) * DD + d0;
#pragma unroll
            for (int i = 0; i < 4; i++) {
                int c = lcbA + i;
                uint32_t d = la * 128 + (((c ^ (la & 7)) & 7) << 4);
                cpa16(st + UG_AHI + d, ah + c * 8);
                cpa16(st + UG_ALO + d, al + c * 8);
                int cb = lcbB + i;
                uint32_t db = lb * 256 + (((((cb ^ (lb & 7)) & 7) | (cb & 8))) << 4);
                cpa16(st + UG_BHI + db, bh + cb * 8);
                cpa16(st + UG_BLO + db, bl + cb * 8);
            }
            cpa_commit();
            cpa_wait<1>();
        } else {
            cpa_wait<0>();
        }
        __syncthreads();
        const uint32_t sb = smb + (kc & 1) * UG_STAGE;
#pragma unroll
        for (int s = 0; s < 4; s++) {
            uint32_t Ah[4][4], Al[4][4], Bh[2][4], Bl[2][4];
            const int ca = s * 2 + ack;
            const int krow = s * 16 + bkrow;
#pragma unroll
            for (int mi = 0; mi < 4; mi++) {
                uint32_t ro = (arow + mi * 16) * 128 + ((ca ^ lsw) << 4);
                ldmx4(Ah[mi], sb + UG_AHI + ro);
                ldmx4(Al[mi], sb + UG_ALO + ro);
            }
#pragma unroll
            for (int n2 = 0; n2 < 2; n2++) {
                const int cn = bcn + n2 * 2;
                const uint32_t co = ((((cn ^ lsw) & 7) | (cn & 8)) << 4);
                ldmx4t(Bh[n2], sb + UG_BHI + krow * 256 + co);
                ldmx4t(Bl[n2], sb + UG_BLO + krow * 256 + co);
            }
#pragma unroll
            for (int mi = 0; mi < 4; mi++)
#pragma unroll
                for (int ni = 0; ni < 4; ni++) {
                    const uint32_t* bp = &Bh[ni >> 1][(ni & 1) * 2];
                    mma_bf16(acc[mi][ni], Ah[mi], bp[0], bp[1]);
                }
#pragma unroll
            for (int mi = 0; mi < 4; mi++)
#pragma unroll
                for (int ni = 0; ni < 4; ni++) {
                    const uint32_t* bp = &Bl[ni >> 1][(ni & 1) * 2];
                    mma_bf16(acc[mi][ni], Ah[mi], bp[0], bp[1]);
                }
#pragma unroll
            for (int mi = 0; mi < 4; mi++)
#pragma unroll
                for (int ni = 0; ni < 4; ni++) {
                    const uint32_t* bp = &Bh[ni >> 1][(ni & 1) * 2];
                    mma_bf16(acc[mi][ni], Al[mi], bp[0], bp[1]);
                }
        }
        __syncthreads();
    }

    // stage U in smem, then coalesced G epilogue
    float* st = (float*)dsm;
    const int g = lane >> 2, tc = (lane & 3) * 2;
#pragma unroll
    for (int mi = 0; mi < 4; mi++) {
        const int r0 = wm * 64 + mi * 16 + g;
#pragma unroll
        for (int ni = 0; ni < 4; ni++) {
            const int cl = wn * 32 + ni * 8 + tc;
            st[r0 * 128 + cl] = acc[mi][ni][0];
            st[r0 * 128 + cl + 1] = acc[mi][ni][1];
            st[(r0 + 8) * 128 + cl] = acc[mi][ni][2];
            st[(r0 + 8) * 128 + cl + 1] = acc[mi][ni][3];
        }
    }
    __syncthreads();
#pragma unroll
    for (int it = 0; it < 16; it++) {
        const int idx = it * 256 + tid;
        const int r = idx >> 5, c4 = (idx & 31) * 4;
        float4 u4 = *(float4*)&st[r * 128 + c4];
        float4 cv = *(const float4*)(C + ((size_t)(b * TT + t0 + r)) * DD + d0 + c4);
        float4 h4 = *(const float4*)&hs[c4];
        float* grow = G + ((size_t)(b * TT + t0 + r)) * (4 * DD);
        *(float4*)(grow + d0 + c4) = cv;
        *(float4*)(grow + DD + d0 + c4) = u4;
        *(float4*)(grow + 2 * DD + d0 + c4) =
            make_float4(cv.x * u4.x, cv.y * u4.y, cv.z * u4.z, cv.w * u4.w);
        *(float4*)(grow + 3 * DD + d0 + c4) =
            make_float4(cv.x * h4.x, cv.y * h4.y, cv.z * h4.z, cv.w * h4.w);
    }
}

// ---------------- launch ----------------------------------------------------
extern "C" void kernel_launch(void* const* d_in, const int* in_sizes, int n_in,
                              void* d_out, int out_size) {
    const float* C  = (const float*)d_in[0];
    const float* Q  = (const float*)d_in[1];
    const float* wa = (const float*)d_in[2];
    float* G = (float*)d_out;

    cudaFuncSetAttribute(k_s_mma, cudaFuncAttributeMaxDynamicSharedMemorySize, 2 * SG_STAGE);
    cudaFuncSetAttribute(k_u_mma, cudaFuncAttributeMaxDynamicSharedMemorySize, 2 * UG_STAGE);

    float* d_c1; cudaGetSymbolAddress((void**)&d_c1, g_c1);
    float* d_q2; cudaGetSymbolAddress((void**)&d_q2, g_q2);

    k_rowdot<<<(BB * TT) / 8, 256>>>(C, wa, d_c1, BB * TT);
    k_rowdot<<<(BB * JJ) / 8, 256>>>(Q, wa + DD, d_q2, BB * JJ);
    k_convC<<<(BB * TT * DD) / 8 / 256, 256>>>(C, wa + 2 * DD);
    k_convQ<<<(BB * JJ * DD) / 8 / 256, 256>>>(Q);

    dim3 gs(JJ / 128, TT / 128, BB);
    k_s_mma<<<gs, 256, 2 * SG_STAGE>>>();

    k_colcombine<<<BB, 256>>>();
    k_bt<<<BB, 256>>>();
    dim3 g2(NCHUNK, BB);
    k_hpart<<<g2, 256>>>(C);
    k_hcombine<<<BB, 512>>>();
    k_psplit<<<(BB * TT * JJ) / 8 / 256, 256>>>();

    dim3 gu(DD / 128, TT / 128, BB);
    k_u_mma<<<gu, 256, 2 * UG_STAGE>>>(C, G);
}

// round 5
// speedup vs baseline: 1.0980x; 1.0980x over previous
#include <cuda_runtime.h>
#include <cuda_bf16.h>
#include <math.h>
#include <stdint.h>

#define BB 32
#define TT 1024
#define JJ 256
#define DD 512
#define NCHUNK 8

// ---------------- scratch (device globals) ----------------------------------
__device__ float g_S[BB * TT * JJ];      // raw S (32 MB)
__device__ float g_c1[BB * TT];
__device__ float g_q2[BB * JJ];
__device__ float g_mp[BB * 2 * TT];      // row-max partials (per j-tile)
__device__ float g_pM[BB * NCHUNK * JJ];
__device__ float g_pZ[BB * NCHUNK * JJ];
__device__ float g_M[BB * JJ];
__device__ float g_invZ[BB * JJ];
__device__ float g_bt[BB * TT];
__device__ float g_hp[BB * NCHUNK * DD];
__device__ float g_h[BB * DD];

// ---------------- helpers ----------------------------------------------------
__device__ __forceinline__ uint32_t smem_u32(const void* p) {
    uint32_t a;
    asm("{ .reg .u64 t; cvta.to.shared.u64 t, %1; cvt.u32.u64 %0, t; }" : "=r"(a) : "l"(p));
    return a;
}
__device__ __forceinline__ void ldmx4(uint32_t* r, uint32_t a) {
    asm volatile("ldmatrix.sync.aligned.m8n8.x4.shared.b16 {%0,%1,%2,%3}, [%4];"
                 : "=r"(r[0]), "=r"(r[1]), "=r"(r[2]), "=r"(r[3]) : "r"(a));
}
__device__ __forceinline__ void ldmx4t(uint32_t* r, uint32_t a) {
    asm volatile("ldmatrix.sync.aligned.m8n8.x4.trans.shared.b16 {%0,%1,%2,%3}, [%4];"
                 : "=r"(r[0]), "=r"(r[1]), "=r"(r[2]), "=r"(r[3]) : "r"(a));
}
__device__ __forceinline__ void mma_bf16(float* c, const uint32_t* a, uint32_t b0, uint32_t b1) {
    asm volatile(
        "mma.sync.aligned.m16n8k16.row.col.f32.bf16.bf16.f32 "
        "{%0,%1,%2,%3}, {%4,%5,%6,%7}, {%8,%9}, {%0,%1,%2,%3};"
        : "+f"(c[0]), "+f"(c[1]), "+f"(c[2]), "+f"(c[3])
        : "r"(a[0]), "r"(a[1]), "r"(a[2]), "r"(a[3]), "r"(b0), "r"(b1));
}
// truncation split: hi = top 16 bits of fp32 (exact bf16), lo = rn(v - hi)
__device__ __forceinline__ void split8(const float* v, uint4* hi, uint4* lo) {
    uint32_t h[4], l[4];
#pragma unroll
    for (int p = 0; p < 4; p++) {
        float v0 = v[2 * p], v1 = v[2 * p + 1];
        uint32_t b0 = __float_as_uint(v0), b1 = __float_as_uint(v1);
        h[p] = __byte_perm(b0, b1, 0x7632);
        float f0 = __uint_as_float(b0 & 0xFFFF0000u);
        float f1 = __uint_as_float(b1 & 0xFFFF0000u);
        float l0 = v0 - f0, l1 = v1 - f1;
        asm("cvt.rn.bf16x2.f32 %0, %1, %2;" : "=r"(l[p]) : "f"(l1), "f"(l0));
    }
    *hi = make_uint4(h[0], h[1], h[2], h[3]);
    *lo = make_uint4(l[0], l[1], l[2], l[3]);
}

// ---------------- K0: row dot products --------------------------------------
__global__ __launch_bounds__(256) void k_rowdot(const float* __restrict__ X,
                                                const float* __restrict__ w,
                                                float* __restrict__ out, int nrows) {
    int warp = (blockIdx.x * 256 + threadIdx.x) >> 5;
    int lane = threadIdx.x & 31;
    if (warp >= nrows) return;
    const float* row = X + (size_t)warp * DD;
    float s = 0.f;
#pragma unroll
    for (int i = 0; i < DD / 32; i++)
        s += row[lane + i * 32] * __ldg(&w[lane + i * 32]);
#pragma unroll
    for (int o = 16; o > 0; o >>= 1) s += __shfl_down_sync(0xffffffffu, s, o);
    if (lane == 0) out[warp] = s;
}

// ---------------- S-GEMM: S[128t x 128j] = (C.*w3)@Q^T + c1 + q2 -------------
// Double-buffered stages: per stage sA 16KB + sB 16KB; 2 stages = 64KB dynamic.
#define SG_STAGE 32768
#define SG_B_OFF 16384
__global__ __launch_bounds__(256) void k_s_mma(const float* __restrict__ C,
                                               const float* __restrict__ Q,
                                               const float* __restrict__ w3) {
    extern __shared__ __align__(16) char dsm[];
    __shared__ float w3s[512];
    __shared__ float c1s[128], q2s[128];
    __shared__ float sRM[4][128];
    __shared__ float sCM[2][128], sCZ[2][128];

    const int tid = threadIdx.x, lane = tid & 31, wid = tid >> 5;
    const int b = blockIdx.z, tb = blockIdx.y, jt = blockIdx.x;
    const int t0 = tb * 128, j0 = jt * 128;

    w3s[tid] = w3[tid];
    w3s[tid + 256] = w3[tid + 256];
    if (tid < 128) {
        c1s[tid] = g_c1[b * TT + t0 + tid];
        q2s[tid] = g_q2[b * JJ + j0 + tid];
    }
    __syncthreads();

    const uint32_t smb = smem_u32(dsm);
    const int sr = tid >> 2, sc = tid & 3;
    const int ssw = sr & 7;
    const float* Ab = C + ((size_t)(b * TT + t0 + sr)) * DD + sc * 8;
    const float* Bb = Q + ((size_t)(b * JJ + j0 + sr)) * DD + sc * 8;
    const uint32_t stsA0 = sr * 128 + ((sc ^ ssw) << 4);
    const uint32_t stsA1 = sr * 128 + (((sc + 4) ^ ssw) << 4);

    float ra[16], rb[16];
    // load chunk 0
    {
        *(float4*)(ra) = *(const float4*)(Ab);
        *(float4*)(ra + 4) = *(const float4*)(Ab + 4);
        *(float4*)(ra + 8) = *(const float4*)(Ab + (size_t)64 * DD);
        *(float4*)(ra + 12) = *(const float4*)(Ab + (size_t)64 * DD + 4);
        *(float4*)(rb) = *(const float4*)(Bb);
        *(float4*)(rb + 4) = *(const float4*)(Bb + 4);
        *(float4*)(rb + 8) = *(const float4*)(Bb + (size_t)64 * DD);
        *(float4*)(rb + 12) = *(const float4*)(Bb + (size_t)64 * DD + 4);
    }
    // convert chunk 0 -> stage 0
    {
        const float* w = &w3s[sc * 8];
        float va[8];
#pragma unroll
        for (int e = 0; e < 8; e++) va[e] = ra[e] * w[e];
        uint4 hi, lo;
        split8(va, &hi, &lo);
        *(uint4*)(dsm + stsA0) = hi;
        *(uint4*)(dsm + stsA1) = lo;
#pragma unroll
        for (int e = 0; e < 8; e++) va[e] = ra[8 + e] * w[e];
        split8(va, &hi, &lo);
        *(uint4*)(dsm + 64 * 128 + stsA0) = hi;
        *(uint4*)(dsm + 64 * 128 + stsA1) = lo;
        split8(rb, &hi, &lo);
        *(uint4*)(dsm + SG_B_OFF + stsA0) = hi;
        *(uint4*)(dsm + SG_B_OFF + stsA1) = lo;
        split8(rb + 8, &hi, &lo);
        *(uint4*)(dsm + SG_B_OFF + 64 * 128 + stsA0) = hi;
        *(uint4*)(dsm + SG_B_OFF + 64 * 128 + stsA1) = lo;
    }
    // load chunk 1
    {
        const float* pa = Ab + 32;
        const float* pb = Bb + 32;
        *(float4*)(ra) = *(const float4*)(pa);
        *(float4*)(ra + 4) = *(const float4*)(pa + 4);
        *(float4*)(ra + 8) = *(const float4*)(pa + (size_t)64 * DD);
        *(float4*)(ra + 12) = *(const float4*)(pa + (size_t)64 * DD + 4);
        *(float4*)(rb) = *(const float4*)(pb);
        *(float4*)(rb + 4) = *(const float4*)(pb + 4);
        *(float4*)(rb + 8) = *(const float4*)(pb + (size_t)64 * DD);
        *(float4*)(rb + 12) = *(const float4*)(pb + (size_t)64 * DD + 4);
    }
    __syncthreads();

    const int wm = wid >> 2, wn = wid & 3;
    float acc[4][4][4];
#pragma unroll
    for (int i = 0; i < 4; i++)
#pragma unroll
        for (int j = 0; j < 4; j++)
#pragma unroll
            for (int e = 0; e < 4; e++) acc[i][j][e] = 0.f;

    const int lsw = lane & 7;
    const int arow = wm * 64 + (lane & 7) + ((lane >> 3) & 1) * 8;
    const int ack = lane >> 4;
    const int brow = wn * 32 + (lane & 7) + ((lane >> 4) & 1) * 8;
    const int bck = (lane >> 3) & 1;

#pragma unroll 1
    for (int kc = 0; kc < 16; kc++) {
        // convert chunk kc+1 into next stage (overlaps with this chunk's MMA issue)
        if (kc < 15) {
            char* st = dsm + ((kc + 1) & 1) * SG_STAGE;
            const float* w = &w3s[(kc + 1) * 32 + sc * 8];
            float va[8];
            uint4 hi, lo;
#pragma unroll
            for (int e = 0; e < 8; e++) va[e] = ra[e] * w[e];
            split8(va, &hi, &lo);
            *(uint4*)(st + stsA0) = hi;
            *(uint4*)(st + stsA1) = lo;
#pragma unroll
            for (int e = 0; e < 8; e++) va[e] = ra[8 + e] * w[e];
            split8(va, &hi, &lo);
            *(uint4*)(st + 64 * 128 + stsA0) = hi;
            *(uint4*)(st + 64 * 128 + stsA1) = lo;
            split8(rb, &hi, &lo);
            *(uint4*)(st + SG_B_OFF + stsA0) = hi;
            *(uint4*)(st + SG_B_OFF + stsA1) = lo;
            split8(rb + 8, &hi, &lo);
            *(uint4*)(st + SG_B_OFF + 64 * 128 + stsA0) = hi;
            *(uint4*)(st + SG_B_OFF + 64 * 128 + stsA1) = lo;
        }
        if (kc < 14) {
            const float* pa = Ab + (kc + 2) * 32;
            const float* pb = Bb + (kc + 2) * 32;
            *(float4*)(ra) = *(const float4*)(pa);
            *(float4*)(ra + 4) = *(const float4*)(pa + 4);
            *(float4*)(ra + 8) = *(const float4*)(pa + (size_t)64 * DD);
            *(float4*)(ra + 12) = *(const float4*)(pa + (size_t)64 * DD + 4);
            *(float4*)(rb) = *(const float4*)(pb);
            *(float4*)(rb + 4) = *(const float4*)(pb + 4);
            *(float4*)(rb + 8) = *(const float4*)(pb + (size_t)64 * DD);
            *(float4*)(rb + 12) = *(const float4*)(pb + (size_t)64 * DD + 4);
        }
        const uint32_t sb = smb + (kc & 1) * SG_STAGE;
#pragma unroll
        for (int ks = 0; ks < 2; ks++) {
            uint32_t Ah[4][4], Al[4][4], Bh[2][4], Bl[2][4];
            const int ca = ks * 2 + ack;
            const int cb = ks * 2 + bck;
#pragma unroll
            for (int mi = 0; mi < 4; mi++) {
                uint32_t ro = (arow + mi * 16) * 128;
                ldmx4(Ah[mi], sb + ro + ((ca ^ lsw) << 4));
                ldmx4(Al[mi], sb + ro + (((ca + 4) ^ lsw) << 4));
            }
#pragma unroll
            for (int n2 = 0; n2 < 2; n2++) {
                uint32_t ro = SG_B_OFF + (brow + n2 * 16) * 128;
                ldmx4(Bh[n2], sb + ro + ((cb ^ lsw) << 4));
                ldmx4(Bl[n2], sb + ro + (((cb + 4) ^ lsw) << 4));
            }
#pragma unroll
            for (int mi = 0; mi < 4; mi++)
#pragma unroll
                for (int ni = 0; ni < 4; ni++) {
                    const uint32_t* bp = &Bh[ni >> 1][(ni & 1) * 2];
                    mma_bf16(acc[mi][ni], Ah[mi], bp[0], bp[1]);
                }
#pragma unroll
            for (int mi = 0; mi < 4; mi++)
#pragma unroll
                for (int ni = 0; ni < 4; ni++) {
                    const uint32_t* bp = &Bl[ni >> 1][(ni & 1) * 2];
                    mma_bf16(acc[mi][ni], Ah[mi], bp[0], bp[1]);
                }
#pragma unroll
            for (int mi = 0; mi < 4; mi++)
#pragma unroll
                for (int ni = 0; ni < 4; ni++) {
                    const uint32_t* bp = &Bh[ni >> 1][(ni & 1) * 2];
                    mma_bf16(acc[mi][ni], Al[mi], bp[0], bp[1]);
                }
        }
        __syncthreads();
    }

    // ---- epilogue: biases, store S, fused row-max + column partial stats ----
    const int g = lane >> 2, tc = (lane & 3) * 2;
#pragma unroll
    for (int mi = 0; mi < 4; mi++) {
        const int tl = wm * 64 + mi * 16 + g;
        const float c1a = c1s[tl], c1b = c1s[tl + 8];
        float* row0 = &g_S[((size_t)(b * TT + t0 + tl)) * JJ + j0];
        float* row1 = row0 + (size_t)8 * JJ;
#pragma unroll
        for (int ni = 0; ni < 4; ni++) {
            const int jl = wn * 32 + ni * 8 + tc;
            const float q2a = q2s[jl], q2b = q2s[jl + 1];
            acc[mi][ni][0] += c1a + q2a;
            acc[mi][ni][1] += c1a + q2b;
            acc[mi][ni][2] += c1b + q2a;
            acc[mi][ni][3] += c1b + q2b;
            *(float2*)(row0 + jl) = make_float2(acc[mi][ni][0], acc[mi][ni][1]);
            *(float2*)(row1 + jl) = make_float2(acc[mi][ni][2], acc[mi][ni][3]);
        }
    }
    // row max over this CTA's 128 j
#pragma unroll
    for (int mi = 0; mi < 4; mi++) {
#pragma unroll
        for (int rr = 0; rr < 2; rr++) {
            float m = -1e30f;
#pragma unroll
            for (int ni = 0; ni < 4; ni++)
                m = fmaxf(m, fmaxf(acc[mi][ni][rr * 2], acc[mi][ni][rr * 2 + 1]));
            m = fmaxf(m, __shfl_xor_sync(0xffffffffu, m, 1));
            m = fmaxf(m, __shfl_xor_sync(0xffffffffu, m, 2));
            if ((lane & 3) == 0) sRM[wn][wm * 64 + mi * 16 + g + rr * 8] = m;
        }
    }
    // column stats (max & sum-exp over this CTA's 128 t)
#pragma unroll
    for (int ni = 0; ni < 4; ni++) {
#pragma unroll
        for (int cc = 0; cc < 2; cc++) {
            float m = -1e30f;
#pragma unroll
            for (int mi = 0; mi < 4; mi++)
                m = fmaxf(m, fmaxf(acc[mi][ni][cc], acc[mi][ni][2 + cc]));
            float z = 0.f;
#pragma unroll
            for (int mi = 0; mi < 4; mi++)
                z += __expf(acc[mi][ni][cc] - m) + __expf(acc[mi][ni][2 + cc] - m);
#pragma unroll
            for (int o = 4; o < 32; o <<= 1) {
                float Mo = __shfl_xor_sync(0xffffffffu, m, o);
                float Zo = __shfl_xor_sync(0xffffffffu, z, o);
                float nm = fmaxf(m, Mo);
                z = z * __expf(m - nm) + Zo * __expf(Mo - nm);
                m = nm;
            }
            if (g == 0) {
                sCM[wm][wn * 32 + ni * 8 + tc + cc] = m;
                sCZ[wm][wn * 32 + ni * 8 + tc + cc] = z;
            }
        }
    }
    __syncthreads();
    if (tid < 128) {
        float m = fmaxf(fmaxf(sRM[0][tid], sRM[1][tid]), fmaxf(sRM[2][tid], sRM[3][tid]));
        g_mp[((size_t)(b * 2 + jt)) * TT + t0 + tid] = m;
        float M0 = sCM[0][tid], M1 = sCM[1][tid];
        float nm = fmaxf(M0, M1);
        float Z = sCZ[0][tid] * __expf(M0 - nm) + sCZ[1][tid] * __expf(M1 - nm);
        g_pM[(b * NCHUNK + tb) * JJ + j0 + tid] = nm;
        g_pZ[(b * NCHUNK + tb) * JJ + j0 + tid] = Z;
    }
}

// ---------------- combine / bt / h -------------------------------------------
__global__ __launch_bounds__(256) void k_colcombine() {
    int b = blockIdx.x, j = threadIdx.x;
    float M = -1e30f;
#pragma unroll
    for (int c = 0; c < NCHUNK; c++) M = fmaxf(M, g_pM[(b * NCHUNK + c) * JJ + j]);
    float Z = 0.f;
#pragma unroll
    for (int c = 0; c < NCHUNK; c++)
        Z += g_pZ[(b * NCHUNK + c) * JJ + j] * __expf(g_pM[(b * NCHUNK + c) * JJ + j] - M);
    g_M[b * JJ + j] = M;
    g_invZ[b * JJ + j] = 1.0f / Z;
}
__global__ __launch_bounds__(256) void k_bt() {
    __shared__ float red[256];
    int b = blockIdx.x, tid = threadIdx.x;
    float mv[4];
#pragma unroll
    for (int i = 0; i < 4; i++) {
        int t = tid + i * 256;
        mv[i] = fmaxf(g_mp[((size_t)(b * 2)) * TT + t], g_mp[((size_t)(b * 2 + 1)) * TT + t]);
    }
    float mx = fmaxf(fmaxf(mv[0], mv[1]), fmaxf(mv[2], mv[3]));
    red[tid] = mx;
    __syncthreads();
    for (int s = 128; s > 0; s >>= 1) {
        if (tid < s) red[tid] = fmaxf(red[tid], red[tid + s]);
        __syncthreads();
    }
    float bmax = red[0];
    __syncthreads();
    float e[4], ssum = 0.f;
#pragma unroll
    for (int i = 0; i < 4; i++) { e[i] = __expf(mv[i] - bmax); ssum += e[i]; }
    red[tid] = ssum;
    __syncthreads();
    for (int s = 128; s > 0; s >>= 1) {
        if (tid < s) red[tid] += red[tid + s];
        __syncthreads();
    }
    float inv = 1.0f / red[0];
#pragma unroll
    for (int i = 0; i < 4; i++) g_bt[b * TT + tid + i * 256] = e[i] * inv;
}
__global__ __launch_bounds__(256) void k_hpart(const float* __restrict__ C) {
    __shared__ float bts[TT / NCHUNK];
    int b = blockIdx.y, chunk = blockIdx.x;
    int tid = threadIdx.x;
    if (tid < TT / NCHUNK) bts[tid] = g_bt[b * TT + chunk * (TT / NCHUNK) + tid];
    __syncthreads();
    float a0 = 0.f, a1 = 0.f;
    for (int tt = 0; tt < TT / NCHUNK; tt++) {
        int t = chunk * (TT / NCHUNK) + tt;
        const float* cr = C + ((size_t)(b * TT + t)) * DD;
        a0 = fmaf(bts[tt], cr[tid], a0);
        a1 = fmaf(bts[tt], cr[tid + 256], a1);
    }
    g_hp[(b * NCHUNK + chunk) * DD + tid] = a0;
    g_hp[(b * NCHUNK + chunk) * DD + tid + 256] = a1;
}
__global__ __launch_bounds__(512) void k_hcombine() {
    int b = blockIdx.x, d = threadIdx.x;
    float s = 0.f;
#pragma unroll
    for (int c = 0; c < NCHUNK; c++) s += g_hp[(b * NCHUNK + c) * DD + d];
    g_h[b * DD + d] = s;
}

// ---------------- U-GEMM: U[128t x 128d] = softmax(S) @ Q, full G epilogue ---
// Per stage: sA 16KB + sBh 8KB + sBl 8KB = 32KB; 2 stages = 64KB dynamic.
#define UG_STAGE 32768
#define UG_BH 16384
#define UG_BL 24576
__global__ __launch_bounds__(256) void k_u_mma(const float* __restrict__ C,
                                               const float* __restrict__ Q,
                                               float* __restrict__ G) {
    extern __shared__ __align__(16) char dsm[];
    __shared__ float Ms[256], iZs[256], hs[128];

    const int tid = threadIdx.x, lane = tid & 31, wid = tid >> 5;
    const int b = blockIdx.z, t0 = blockIdx.y * 128, d0 = blockIdx.x * 128;

    Ms[tid] = g_M[b * JJ + tid];
    iZs[tid] = g_invZ[b * JJ + tid];
    if (tid < 128) hs[tid] = g_h[b * DD + d0 + tid];
    __syncthreads();

    const uint32_t smb = smem_u32(dsm);
    const int sr = tid >> 2, sc = tid & 3;
    const int ssw = sr & 7;
    const int rB = tid >> 4, cB = tid & 15;
    const int bsw = rB & 7;
    const float* Sb = g_S + ((size_t)(b * TT + t0 + sr)) * JJ + sc * 8;
    const float* Qb = Q + ((size_t)(b * JJ + rB)) * DD + d0 + cB * 8;
    const uint32_t stsA0 = sr * 128 + ((sc ^ ssw) << 4);
    const uint32_t stsA1 = sr * 128 + (((sc + 4) ^ ssw) << 4);
    const uint32_t stsB = (((cB ^ bsw) & 7) | (cB & 8)) << 4;

    float ra[16], rb[16];
    {
        *(float4*)(ra) = *(const float4*)(Sb);
        *(float4*)(ra + 4) = *(const float4*)(Sb + 4);
        *(float4*)(ra + 8) = *(const float4*)(Sb + (size_t)64 * JJ);
        *(float4*)(ra + 12) = *(const float4*)(Sb + (size_t)64 * JJ + 4);
        *(float4*)(rb) = *(const float4*)(Qb);
        *(float4*)(rb + 4) = *(const float4*)(Qb + 4);
        *(float4*)(rb + 8) = *(const float4*)(Qb + (size_t)16 * DD);
        *(float4*)(rb + 12) = *(const float4*)(Qb + (size_t)16 * DD + 4);
    }
    {
        const int jb = sc * 8;
        float va[8];
        uint4 hi, lo;
#pragma unroll
        for (int e = 0; e < 8; e++) va[e] = __expf(ra[e] - Ms[jb + e]) * iZs[jb + e];
        split8(va, &hi, &lo);
        *(uint4*)(dsm + stsA0) = hi;
        *(uint4*)(dsm + stsA1) = lo;
#pragma unroll
        for (int e = 0; e < 8; e++) va[e] = __expf(ra[8 + e] - Ms[jb + e]) * iZs[jb + e];
        split8(va, &hi, &lo);
        *(uint4*)(dsm + 64 * 128 + stsA0) = hi;
        *(uint4*)(dsm + 64 * 128 + stsA1) = lo;
        split8(rb, &hi, &lo);
        *(uint4*)(dsm + UG_BH + rB * 256 + stsB) = hi;
        *(uint4*)(dsm + UG_BL + rB * 256 + stsB) = lo;
        split8(rb + 8, &hi, &lo);
        *(uint4*)(dsm + UG_BH + (rB + 16) * 256 + stsB) = hi;
        *(uint4*)(dsm + UG_BL + (rB + 16) * 256 + stsB) = lo;
    }
    {
        const float* pa = Sb + 32;
        const float* pb = Qb + (size_t)32 * DD;
        *(float4*)(ra) = *(const float4*)(pa);
        *(float4*)(ra + 4) = *(const float4*)(pa + 4);
        *(float4*)(ra + 8) = *(const float4*)(pa + (size_t)64 * JJ);
        *(float4*)(ra + 12) = *(const float4*)(pa + (size_t)64 * JJ + 4);
        *(float4*)(rb) = *(const float4*)(pb);
        *(float4*)(rb + 4) = *(const float4*)(pb + 4);
        *(float4*)(rb + 8) = *(const float4*)(pb + (size_t)16 * DD);
        *(float4*)(rb + 12) = *(const float4*)(pb + (size_t)16 * DD + 4);
    }
    __syncthreads();

    const int wm = wid >> 2, wn = wid & 3;
    float acc[4][4][4];
#pragma unroll
    for (int i = 0; i < 4; i++)
#pragma unroll
        for (int j = 0; j < 4; j++)
#pragma unroll
            for (int e = 0; e < 4; e++) acc[i][j][e] = 0.f;

    const int lsw = lane & 7;
    const int arow = wm * 64 + (lane & 7) + ((lane >> 3) & 1) * 8;
    const int ack = lane >> 4;
    const int bkrow = (lane & 7) + ((lane >> 3) & 1) * 8;
    const int bcn = wn * 4 + (lane >> 4);

#pragma unroll 1
    for (int kc = 0; kc < 8; kc++) {
        if (kc < 7) {
            char* st = dsm + ((kc + 1) & 1) * UG_STAGE;
            const int jb = (kc + 1) * 32 + sc * 8;
            float va[8];
            uint4 hi, lo;
#pragma unroll
            for (int e = 0; e < 8; e++) va[e] = __expf(ra[e] - Ms[jb + e]) * iZs[jb + e];
            split8(va, &hi, &lo);
            *(uint4*)(st + stsA0) = hi;
            *(uint4*)(st + stsA1) = lo;
#pragma unroll
            for (int e = 0; e < 8; e++) va[e] = __expf(ra[8 + e] - Ms[jb + e]) * iZs[jb + e];
            split8(va, &hi, &lo);
            *(uint4*)(st + 64 * 128 + stsA0) = hi;
            *(uint4*)(st + 64 * 128 + stsA1) = lo;
            split8(rb, &hi, &lo);
            *(uint4*)(st + UG_BH + rB * 256 + stsB) = hi;
            *(uint4*)(st + UG_BL + rB * 256 + stsB) = lo;
            split8(rb + 8, &hi, &lo);
            *(uint4*)(st + UG_BH + (rB + 16) * 256 + stsB) = hi;
            *(uint4*)(st + UG_BL + (rB + 16) * 256 + stsB) = lo;
        }
        if (kc < 6) {
            const float* pa = Sb + (kc + 2) * 32;
            const float* pb = Qb + (size_t)(kc + 2) * 32 * DD;
            *(float4*)(ra) = *(const float4*)(pa);
            *(float4*)(ra + 4) = *(const float4*)(pa + 4);
            *(float4*)(ra + 8) = *(const float4*)(pa + (size_t)64 * JJ);
            *(float4*)(ra + 12) = *(const float4*)(pa + (size_t)64 * JJ + 4);
            *(float4*)(rb) = *(const float4*)(pb);
            *(float4*)(rb + 4) = *(const float4*)(pb + 4);
            *(float4*)(rb + 8) = *(const float4*)(pb + (size_t)16 * DD);
            *(float4*)(rb + 12) = *(const float4*)(pb + (size_t)16 * DD + 4);
        }
        const uint32_t sb = smb + (kc & 1) * UG_STAGE;
#pragma unroll
        for (int ks = 0; ks < 2; ks++) {
            uint32_t Ah[4][4], Al[4][4], Bh[2][4], Bl[2][4];
            const int ca = ks * 2 + ack;
            const int krow = ks * 16 + bkrow;
#pragma unroll
            for (int mi = 0; mi < 4; mi++) {
                uint32_t ro = (arow + mi * 16) * 128;
                ldmx4(Ah[mi], sb + ro + ((ca ^ lsw) << 4));
                ldmx4(Al[mi], sb + ro + (((ca + 4) ^ lsw) << 4));
            }
#pragma unroll
            for (int n2 = 0; n2 < 2; n2++) {
                const int cn = bcn + n2 * 2;
                const uint32_t co = ((((cn ^ lsw) & 7) | (cn & 8)) << 4);
                ldmx4t(Bh[n2], sb + UG_BH + krow * 256 + co);
                ldmx4t(Bl[n2], sb + UG_BL + krow * 256 + co);
            }
#pragma unroll
            for (int mi = 0; mi < 4; mi++)
#pragma unroll
                for (int ni = 0; ni < 4; ni++) {
                    const uint32_t* bp = &Bh[ni >> 1][(ni & 1) * 2];
                    mma_bf16(acc[mi][ni], Ah[mi], bp[0], bp[1]);
                }
#pragma unroll
            for (int mi = 0; mi < 4; mi++)
#pragma unroll
                for (int ni = 0; ni < 4; ni++) {
                    const uint32_t* bp = &Bl[ni >> 1][(ni & 1) * 2];
                    mma_bf16(acc[mi][ni], Ah[mi], bp[0], bp[1]);
                }
#pragma unroll
            for (int mi = 0; mi < 4; mi++)
#pragma unroll
                for (int ni = 0; ni < 4; ni++) {
                    const uint32_t* bp = &Bh[ni >> 1][(ni & 1) * 2];
                    mma_bf16(acc[mi][ni], Al[mi], bp[0], bp[1]);
                }
        }
        __syncthreads();
    }

    // stage U in smem, then coalesced G epilogue
    float* st = (float*)dsm;
    const int g = lane >> 2, tc = (lane & 3) * 2;
#pragma unroll
    for (int mi = 0; mi < 4; mi++) {
        const int r0 = wm * 64 + mi * 16 + g;
#pragma unroll
        for (int ni = 0; ni < 4; ni++) {
            const int cl = wn * 32 + ni * 8 + tc;
            st[r0 * 128 + cl] = acc[mi][ni][0];
            st[r0 * 128 + cl + 1] = acc[mi][ni][1];
            st[(r0 + 8) * 128 + cl] = acc[mi][ni][2];
            st[(r0 + 8) * 128 + cl + 1] = acc[mi][ni][3];
        }
    }
    __syncthreads();
#pragma unroll
    for (int it = 0; it < 16; it++) {
        const int idx = it * 256 + tid;
        const int r = idx >> 5, c4 = (idx & 31) * 4;
        float4 u4 = *(float4*)&st[r * 128 + c4];
        float4 cv = *(const float4*)(C + ((size_t)(b * TT + t0 + r)) * DD + d0 + c4);
        float4 h4 = *(const float4*)&hs[c4];
        float* grow = G + ((size_t)(b * TT + t0 + r)) * (4 * DD);
        *(float4*)(grow + d0 + c4) = cv;
        *(float4*)(grow + DD + d0 + c4) = u4;
        *(float4*)(grow + 2 * DD + d0 + c4) =
            make_float4(cv.x * u4.x, cv.y * u4.y, cv.z * u4.z, cv.w * u4.w);
        *(float4*)(grow + 3 * DD + d0 + c4) =
            make_float4(cv.x * h4.x, cv.y * h4.y, cv.z * h4.z, cv.w * h4.w);
    }
}

// ---------------- launch ----------------------------------------------------
extern "C" void kernel_launch(void* const* d_in, const int* in_sizes, int n_in,
                              void* d_out, int out_size) {
    const float* C  = (const float*)d_in[0];
    const float* Q  = (const float*)d_in[1];
    const float* wa = (const float*)d_in[2];
    float* G = (float*)d_out;

    cudaFuncSetAttribute(k_s_mma, cudaFuncAttributeMaxDynamicSharedMemorySize, 2 * SG_STAGE);
    cudaFuncSetAttribute(k_u_mma, cudaFuncAttributeMaxDynamicSharedMemorySize, 2 * UG_STAGE);

    float* d_c1; cudaGetSymbolAddress((void**)&d_c1, g_c1);
    float* d_q2; cudaGetSymbolAddress((void**)&d_q2, g_q2);

    k_rowdot<<<(BB * TT) / 8, 256>>>(C, wa, d_c1, BB * TT);
    k_rowdot<<<(BB * JJ) / 8, 256>>>(Q, wa + DD, d_q2, BB * JJ);

    dim3 gs(JJ / 128, TT / 128, BB);
    k_s_mma<<<gs, 256, 2 * SG_STAGE>>>(C, Q, wa + 2 * DD);

    k_colcombine<<<BB, 256>>>();
    k_bt<<<BB, 256>>>();
    dim3 g2(NCHUNK, BB);
    k_hpart<<<g2, 256>>>(C);
    k_hcombine<<<BB, 512>>>();

    dim3 gu(DD / 128, TT / 128, BB);
    k_u_mma<<<gu, 256, 2 * UG_STAGE>>>(C, Q, G);
}

// round 6
// speedup vs baseline: 1.1978x; 1.0909x over previous
#include <cuda_runtime.h>
#include <cuda_bf16.h>
#include <cuda_fp16.h>
#include <math.h>
#include <stdint.h>

#define BB 32
#define TT 1024
#define JJ 256
#define DD 512
#define NCHUNK 8

// ---------------- scratch (device globals) ----------------------------------
__device__ float g_S[BB * TT * JJ];      // raw S (32 MB)
__device__ float g_c1[BB * TT];
__device__ float g_q2[BB * JJ];
__device__ float g_mp[BB * 2 * TT];      // row-max partials (per j-tile)
__device__ float g_pM[BB * NCHUNK * JJ];
__device__ float g_pZ[BB * NCHUNK * JJ];
__device__ float g_M[BB * JJ];
__device__ float g_invZ[BB * JJ];
__device__ float g_bt[BB * TT];
__device__ float g_hp[BB * NCHUNK * DD];
__device__ float g_h[BB * DD];

// ---------------- helpers ----------------------------------------------------
__device__ __forceinline__ uint32_t smem_u32(const void* p) {
    uint32_t a;
    asm("{ .reg .u64 t; cvta.to.shared.u64 t, %1; cvt.u32.u64 %0, t; }" : "=r"(a) : "l"(p));
    return a;
}
__device__ __forceinline__ void ldmx4(uint32_t* r, uint32_t a) {
    asm volatile("ldmatrix.sync.aligned.m8n8.x4.shared.b16 {%0,%1,%2,%3}, [%4];"
                 : "=r"(r[0]), "=r"(r[1]), "=r"(r[2]), "=r"(r[3]) : "r"(a));
}
__device__ __forceinline__ void ldmx4t(uint32_t* r, uint32_t a) {
    asm volatile("ldmatrix.sync.aligned.m8n8.x4.trans.shared.b16 {%0,%1,%2,%3}, [%4];"
                 : "=r"(r[0]), "=r"(r[1]), "=r"(r[2]), "=r"(r[3]) : "r"(a));
}
__device__ __forceinline__ void mma_f16(float* c, const uint32_t* a, uint32_t b0, uint32_t b1) {
    asm volatile(
        "mma.sync.aligned.m16n8k16.row.col.f32.f16.f16.f32 "
        "{%0,%1,%2,%3}, {%4,%5,%6,%7}, {%8,%9}, {%0,%1,%2,%3};"
        : "+f"(c[0]), "+f"(c[1]), "+f"(c[2]), "+f"(c[3])
        : "r"(a[0]), "r"(a[1]), "r"(a[2]), "r"(a[3]), "r"(b0), "r"(b1));
}
// fp16 split: hi = rn(v), lo = rn(v - hi)
__device__ __forceinline__ void splitf16_8(const float* v, uint4* hi, uint4* lo) {
    uint32_t h[4], l[4];
#pragma unroll
    for (int p = 0; p < 4; p++) {
        float v0 = v[2 * p], v1 = v[2 * p + 1];
        uint32_t hp;
        asm("cvt.rn.f16x2.f32 %0, %1, %2;" : "=r"(hp) : "f"(v1), "f"(v0));
        h[p] = hp;
        __half2 hh = *reinterpret_cast<__half2*>(&hp);
        float f0 = __low2float(hh), f1 = __high2float(hh);
        asm("cvt.rn.f16x2.f32 %0, %1, %2;" : "=r"(l[p]) : "f"(v1 - f1), "f"(v0 - f0));
    }
    *hi = make_uint4(h[0], h[1], h[2], h[3]);
    *lo = make_uint4(l[0], l[1], l[2], l[3]);
}
// fp16 hi only
__device__ __forceinline__ void cvtf16_8(const float* v, uint4* hi) {
    uint32_t h[4];
#pragma unroll
    for (int p = 0; p < 4; p++)
        asm("cvt.rn.f16x2.f32 %0, %1, %2;" : "=r"(h[p]) : "f"(v[2 * p + 1]), "f"(v[2 * p]));
    *hi = make_uint4(h[0], h[1], h[2], h[3]);
}

// ---------------- K0: row dot products --------------------------------------
__global__ __launch_bounds__(256) void k_rowdot(const float* __restrict__ X,
                                                const float* __restrict__ w,
                                                float* __restrict__ out, int nrows) {
    int warp = (blockIdx.x * 256 + threadIdx.x) >> 5;
    int lane = threadIdx.x & 31;
    if (warp >= nrows) return;
    const float* row = X + (size_t)warp * DD;
    float s = 0.f;
#pragma unroll
    for (int i = 0; i < DD / 32; i++)
        s += row[lane + i * 32] * __ldg(&w[lane + i * 32]);
#pragma unroll
    for (int o = 16; o > 0; o >>= 1) s += __shfl_down_sync(0xffffffffu, s, o);
    if (lane == 0) out[warp] = s;
}

// ---------------- S-GEMM: S[128t x 128j] = (C.*w3)@Q^T + c1 + q2 -------------
// Stage: A (hi+lo interleaved, 128 rows x 128B) 16KB + B-hi (128 rows x 64B) 8KB.
#define SG_STAGE 24576
#define SG_B_OFF 16384
__global__ __launch_bounds__(256) void k_s_mma(const float* __restrict__ C,
                                               const float* __restrict__ Q,
                                               const float* __restrict__ w3) {
    extern __shared__ __align__(16) char dsm[];
    __shared__ float w3s[512];
    __shared__ float c1s[128], q2s[128];
    __shared__ float sRM[4][128];
    __shared__ float sCM[2][128], sCZ[2][128];

    const int tid = threadIdx.x, lane = tid & 31, wid = tid >> 5;
    const int b = blockIdx.z, tb = blockIdx.y, jt = blockIdx.x;
    const int t0 = tb * 128, j0 = jt * 128;

    w3s[tid] = w3[tid];
    w3s[tid + 256] = w3[tid + 256];
    if (tid < 128) {
        c1s[tid] = g_c1[b * TT + t0 + tid];
        q2s[tid] = g_q2[b * JJ + j0 + tid];
    }
    __syncthreads();

    const uint32_t smb = smem_u32(dsm);
    const int sr = tid >> 2, sc = tid & 3;
    const int ssw = sr & 7;
    const float* Ab = C + ((size_t)(b * TT + t0 + sr)) * DD + sc * 8;
    const float* Bb = Q + ((size_t)(b * JJ + j0 + sr)) * DD + sc * 8;
    const uint32_t stsA0 = sr * 128 + ((sc ^ ssw) << 4);
    const uint32_t stsA1 = sr * 128 + (((sc + 4) ^ ssw) << 4);
    const uint32_t stsB0 = SG_B_OFF + sr * 64 + ((sc ^ ((sr >> 1) & 3)) << 4);
    const uint32_t stsB1 = stsB0 + 64 * 64;

    float ra[16], rb[16];
    // load chunk 0
    {
        *(float4*)(ra) = *(const float4*)(Ab);
        *(float4*)(ra + 4) = *(const float4*)(Ab + 4);
        *(float4*)(ra + 8) = *(const float4*)(Ab + (size_t)64 * DD);
        *(float4*)(ra + 12) = *(const float4*)(Ab + (size_t)64 * DD + 4);
        *(float4*)(rb) = *(const float4*)(Bb);
        *(float4*)(rb + 4) = *(const float4*)(Bb + 4);
        *(float4*)(rb + 8) = *(const float4*)(Bb + (size_t)64 * DD);
        *(float4*)(rb + 12) = *(const float4*)(Bb + (size_t)64 * DD + 4);
    }
    // convert chunk 0 -> stage 0
    {
        const float* w = &w3s[sc * 8];
        float va[8];
        uint4 hi, lo;
#pragma unroll
        for (int e = 0; e < 8; e++) va[e] = ra[e] * w[e];
        splitf16_8(va, &hi, &lo);
        *(uint4*)(dsm + stsA0) = hi;
        *(uint4*)(dsm + stsA1) = lo;
#pragma unroll
        for (int e = 0; e < 8; e++) va[e] = ra[8 + e] * w[e];
        splitf16_8(va, &hi, &lo);
        *(uint4*)(dsm + 64 * 128 + stsA0) = hi;
        *(uint4*)(dsm + 64 * 128 + stsA1) = lo;
        cvtf16_8(rb, &hi);
        *(uint4*)(dsm + stsB0) = hi;
        cvtf16_8(rb + 8, &hi);
        *(uint4*)(dsm + stsB1) = hi;
    }
    // load chunk 1
    {
        const float* pa = Ab + 32;
        const float* pb = Bb + 32;
        *(float4*)(ra) = *(const float4*)(pa);
        *(float4*)(ra + 4) = *(const float4*)(pa + 4);
        *(float4*)(ra + 8) = *(const float4*)(pa + (size_t)64 * DD);
        *(float4*)(ra + 12) = *(const float4*)(pa + (size_t)64 * DD + 4);
        *(float4*)(rb) = *(const float4*)(pb);
        *(float4*)(rb + 4) = *(const float4*)(pb + 4);
        *(float4*)(rb + 8) = *(const float4*)(pb + (size_t)64 * DD);
        *(float4*)(rb + 12) = *(const float4*)(pb + (size_t)64 * DD + 4);
    }
    __syncthreads();

    const int wm = wid >> 2, wn = wid & 3;
    float acc[4][4][4];
#pragma unroll
    for (int i = 0; i < 4; i++)
#pragma unroll
        for (int j = 0; j < 4; j++)
#pragma unroll
            for (int e = 0; e < 4; e++) acc[i][j][e] = 0.f;

    const int lsw = lane & 7;
    const int arow = wm * 64 + (lane & 7) + ((lane >> 3) & 1) * 8;
    const int ack = lane >> 4;
    const int bj = wn * 32 + (lane & 7) + ((lane >> 4) & 1) * 8;   // j row (lane-mapped)
    const int bsw3 = (bj >> 1) & 3;                                 // invariant under +16
    const int bck = (lane >> 3) & 1;

#pragma unroll 1
    for (int kc = 0; kc < 16; kc++) {
        // convert chunk kc+1 into next stage (overlaps with this chunk's MMA issue)
        if (kc < 15) {
            char* st = dsm + ((kc + 1) & 1) * SG_STAGE;
            const float* w = &w3s[(kc + 1) * 32 + sc * 8];
            float va[8];
            uint4 hi, lo;
#pragma unroll
            for (int e = 0; e < 8; e++) va[e] = ra[e] * w[e];
            splitf16_8(va, &hi, &lo);
            *(uint4*)(st + stsA0) = hi;
            *(uint4*)(st + stsA1) = lo;
#pragma unroll
            for (int e = 0; e < 8; e++) va[e] = ra[8 + e] * w[e];
            splitf16_8(va, &hi, &lo);
            *(uint4*)(st + 64 * 128 + stsA0) = hi;
            *(uint4*)(st + 64 * 128 + stsA1) = lo;
            cvtf16_8(rb, &hi);
            *(uint4*)(st + stsB0) = hi;
            cvtf16_8(rb + 8, &hi);
            *(uint4*)(st + stsB1) = hi;
        }
        if (kc < 14) {
            const float* pa = Ab + (kc + 2) * 32;
            const float* pb = Bb + (kc + 2) * 32;
            *(float4*)(ra) = *(const float4*)(pa);
            *(float4*)(ra + 4) = *(const float4*)(pa + 4);
            *(float4*)(ra + 8) = *(const float4*)(pa + (size_t)64 * DD);
            *(float4*)(ra + 12) = *(const float4*)(pa + (size_t)64 * DD + 4);
            *(float4*)(rb) = *(const float4*)(pb);
            *(float4*)(rb + 4) = *(const float4*)(pb + 4);
            *(float4*)(rb + 8) = *(const float4*)(pb + (size_t)64 * DD);
            *(float4*)(rb + 12) = *(const float4*)(pb + (size_t)64 * DD + 4);
        }
        const uint32_t sb = smb + (kc & 1) * SG_STAGE;
#pragma unroll
        for (int ks = 0; ks < 2; ks++) {
            uint32_t Ah[4][4], Al[4][4], Bf[2][4];
            const int ca = ks * 2 + ack;
            const int cb = ks * 2 + bck;
#pragma unroll
            for (int mi = 0; mi < 4; mi++) {
                uint32_t ro = (arow + mi * 16) * 128;
                ldmx4(Ah[mi], sb + ro + ((ca ^ lsw) << 4));
                ldmx4(Al[mi], sb + ro + (((ca + 4) ^ lsw) << 4));
            }
#pragma unroll
            for (int n2 = 0; n2 < 2; n2++) {
                uint32_t ro = SG_B_OFF + (uint32_t)(bj + n2 * 16) * 64 + ((cb ^ bsw3) << 4);
                ldmx4(Bf[n2], sb + ro);
            }
#pragma unroll
            for (int mi = 0; mi < 4; mi++)
#pragma unroll
                for (int ni = 0; ni < 4; ni++) {
                    const uint32_t* bp = &Bf[ni >> 1][(ni & 1) * 2];
                    mma_f16(acc[mi][ni], Ah[mi], bp[0], bp[1]);
                }
#pragma unroll
            for (int mi = 0; mi < 4; mi++)
#pragma unroll
                for (int ni = 0; ni < 4; ni++) {
                    const uint32_t* bp = &Bf[ni >> 1][(ni & 1) * 2];
                    mma_f16(acc[mi][ni], Al[mi], bp[0], bp[1]);
                }
        }
        __syncthreads();
    }

    // ---- epilogue: biases, store S, fused row-max + column partial stats ----
    const int g = lane >> 2, tc = (lane & 3) * 2;
#pragma unroll
    for (int mi = 0; mi < 4; mi++) {
        const int tl = wm * 64 + mi * 16 + g;
        const float c1a = c1s[tl], c1b = c1s[tl + 8];
        float* row0 = &g_S[((size_t)(b * TT + t0 + tl)) * JJ + j0];
        float* row1 = row0 + (size_t)8 * JJ;
#pragma unroll
        for (int ni = 0; ni < 4; ni++) {
            const int jl = wn * 32 + ni * 8 + tc;
            const float q2a = q2s[jl], q2b = q2s[jl + 1];
            acc[mi][ni][0] += c1a + q2a;
            acc[mi][ni][1] += c1a + q2b;
            acc[mi][ni][2] += c1b + q2a;
            acc[mi][ni][3] += c1b + q2b;
            *(float2*)(row0 + jl) = make_float2(acc[mi][ni][0], acc[mi][ni][1]);
            *(float2*)(row1 + jl) = make_float2(acc[mi][ni][2], acc[mi][ni][3]);
        }
    }
    // row max over this CTA's 128 j
#pragma unroll
    for (int mi = 0; mi < 4; mi++) {
#pragma unroll
        for (int rr = 0; rr < 2; rr++) {
            float m = -1e30f;
#pragma unroll
            for (int ni = 0; ni < 4; ni++)
                m = fmaxf(m, fmaxf(acc[mi][ni][rr * 2], acc[mi][ni][rr * 2 + 1]));
            m = fmaxf(m, __shfl_xor_sync(0xffffffffu, m, 1));
            m = fmaxf(m, __shfl_xor_sync(0xffffffffu, m, 2));
            if ((lane & 3) == 0) sRM[wn][wm * 64 + mi * 16 + g + rr * 8] = m;
        }
    }
    // column stats (max & sum-exp over this CTA's 128 t)
#pragma unroll
    for (int ni = 0; ni < 4; ni++) {
#pragma unroll
        for (int cc = 0; cc < 2; cc++) {
            float m = -1e30f;
#pragma unroll
            for (int mi = 0; mi < 4; mi++)
                m = fmaxf(m, fmaxf(acc[mi][ni][cc], acc[mi][ni][2 + cc]));
            float z = 0.f;
#pragma unroll
            for (int mi = 0; mi < 4; mi++)
                z += __expf(acc[mi][ni][cc] - m) + __expf(acc[mi][ni][2 + cc] - m);
#pragma unroll
            for (int o = 4; o < 32; o <<= 1) {
                float Mo = __shfl_xor_sync(0xffffffffu, m, o);
                float Zo = __shfl_xor_sync(0xffffffffu, z, o);
                float nm = fmaxf(m, Mo);
                z = z * __expf(m - nm) + Zo * __expf(Mo - nm);
                m = nm;
            }
            if (g == 0) {
                sCM[wm][wn * 32 + ni * 8 + tc + cc] = m;
                sCZ[wm][wn * 32 + ni * 8 + tc + cc] = z;
            }
        }
    }
    __syncthreads();
    if (tid < 128) {
        float m = fmaxf(fmaxf(sRM[0][tid], sRM[1][tid]), fmaxf(sRM[2][tid], sRM[3][tid]));
        g_mp[((size_t)(b * 2 + jt)) * TT + t0 + tid] = m;
        float M0 = sCM[0][tid], M1 = sCM[1][tid];
        float nm = fmaxf(M0, M1);
        float Z = sCZ[0][tid] * __expf(M0 - nm) + sCZ[1][tid] * __expf(M1 - nm);
        g_pM[(b * NCHUNK + tb) * JJ + j0 + tid] = nm;
        g_pZ[(b * NCHUNK + tb) * JJ + j0 + tid] = Z;
    }
}

// ---------------- combine / bt / h -------------------------------------------
__global__ __launch_bounds__(256) void k_colcombine() {
    int b = blockIdx.x, j = threadIdx.x;
    float M = -1e30f;
#pragma unroll
    for (int c = 0; c < NCHUNK; c++) M = fmaxf(M, g_pM[(b * NCHUNK + c) * JJ + j]);
    float Z = 0.f;
#pragma unroll
    for (int c = 0; c < NCHUNK; c++)
        Z += g_pZ[(b * NCHUNK + c) * JJ + j] * __expf(g_pM[(b * NCHUNK + c) * JJ + j] - M);
    g_M[b * JJ + j] = M;
    g_invZ[b * JJ + j] = 1.0f / Z;
}
__global__ __launch_bounds__(256) void k_bt() {
    __shared__ float red[256];
    int b = blockIdx.x, tid = threadIdx.x;
    float mv[4];
#pragma unroll
    for (int i = 0; i < 4; i++) {
        int t = tid + i * 256;
        mv[i] = fmaxf(g_mp[((size_t)(b * 2)) * TT + t], g_mp[((size_t)(b * 2 + 1)) * TT + t]);
    }
    float mx = fmaxf(fmaxf(mv[0], mv[1]), fmaxf(mv[2], mv[3]));
    red[tid] = mx;
    __syncthreads();
    for (int s = 128; s > 0; s >>= 1) {
        if (tid < s) red[tid] = fmaxf(red[tid], red[tid + s]);
        __syncthreads();
    }
    float bmax = red[0];
    __syncthreads();
    float e[4], ssum = 0.f;
#pragma unroll
    for (int i = 0; i < 4; i++) { e[i] = __expf(mv[i] - bmax); ssum += e[i]; }
    red[tid] = ssum;
    __syncthreads();
    for (int s = 128; s > 0; s >>= 1) {
        if (tid < s) red[tid] += red[tid + s];
        __syncthreads();
    }
    float inv = 1.0f / red[0];
#pragma unroll
    for (int i = 0; i < 4; i++) g_bt[b * TT + tid + i * 256] = e[i] * inv;
}
__global__ __launch_bounds__(256) void k_hpart(const float* __restrict__ C) {
    __shared__ float bts[TT / NCHUNK];
    int b = blockIdx.y, chunk = blockIdx.x;
    int tid = threadIdx.x;
    if (tid < TT / NCHUNK) bts[tid] = g_bt[b * TT + chunk * (TT / NCHUNK) + tid];
    __syncthreads();
    float a0 = 0.f, a1 = 0.f;
    for (int tt = 0; tt < TT / NCHUNK; tt++) {
        int t = chunk * (TT / NCHUNK) + tt;
        const float* cr = C + ((size_t)(b * TT + t)) * DD;
        a0 = fmaf(bts[tt], cr[tid], a0);
        a1 = fmaf(bts[tt], cr[tid + 256], a1);
    }
    g_hp[(b * NCHUNK + chunk) * DD + tid] = a0;
    g_hp[(b * NCHUNK + chunk) * DD + tid + 256] = a1;
}
__global__ __launch_bounds__(512) void k_hcombine() {
    int b = blockIdx.x, d = threadIdx.x;
    float s = 0.f;
#pragma unroll
    for (int c = 0; c < NCHUNK; c++) s += g_hp[(b * NCHUNK + c) * DD + d];
    g_h[b * DD + d] = s;
}

// ---------------- U-GEMM: U[128t x 128d] = softmax(S) @ Q, full G epilogue ---
// Stage: A (hi+lo) 16KB + B-hi (32 k-rows x 256B) 8KB = 24KB; 2 stages.
#define UG_STAGE 24576
#define UG_BH 16384
__global__ __launch_bounds__(256) void k_u_mma(const float* __restrict__ C,
                                               const float* __restrict__ Q,
                                               float* __restrict__ G) {
    extern __shared__ __align__(16) char dsm[];
    __shared__ float Ms[256], iZs[256], hs[128];

    const int tid = threadIdx.x, lane = tid & 31, wid = tid >> 5;
    const int b = blockIdx.z, t0 = blockIdx.y * 128, d0 = blockIdx.x * 128;

    Ms[tid] = g_M[b * JJ + tid];
    iZs[tid] = g_invZ[b * JJ + tid];
    if (tid < 128) hs[tid] = g_h[b * DD + d0 + tid];
    __syncthreads();

    const uint32_t smb = smem_u32(dsm);
    const int sr = tid >> 2, sc = tid & 3;
    const int ssw = sr & 7;
    const int rB = tid >> 4, cB = tid & 15;
    const int bsw = rB & 7;
    const float* Sb = g_S + ((size_t)(b * TT + t0 + sr)) * JJ + sc * 8;
    const float* Qb = Q + ((size_t)(b * JJ + rB)) * DD + d0 + cB * 8;
    const uint32_t stsA0 = sr * 128 + ((sc ^ ssw) << 4);
    const uint32_t stsA1 = sr * 128 + (((sc + 4) ^ ssw) << 4);
    const uint32_t stsB = (((cB ^ bsw) & 7) | (cB & 8)) << 4;

    float ra[16], rb[16];
    {
        *(float4*)(ra) = *(const float4*)(Sb);
        *(float4*)(ra + 4) = *(const float4*)(Sb + 4);
        *(float4*)(ra + 8) = *(const float4*)(Sb + (size_t)64 * JJ);
        *(float4*)(ra + 12) = *(const float4*)(Sb + (size_t)64 * JJ + 4);
        *(float4*)(rb) = *(const float4*)(Qb);
        *(float4*)(rb + 4) = *(const float4*)(Qb + 4);
        *(float4*)(rb + 8) = *(const float4*)(Qb + (size_t)16 * DD);
        *(float4*)(rb + 12) = *(const float4*)(Qb + (size_t)16 * DD + 4);
    }
    {
        const int jb = sc * 8;
        float va[8];
        uint4 hi, lo;
#pragma unroll
        for (int e = 0; e < 8; e++) va[e] = __expf(ra[e] - Ms[jb + e]) * iZs[jb + e];
        splitf16_8(va, &hi, &lo);
        *(uint4*)(dsm + stsA0) = hi;
        *(uint4*)(dsm + stsA1) = lo;
#pragma unroll
        for (int e = 0; e < 8; e++) va[e] = __expf(ra[8 + e] - Ms[jb + e]) * iZs[jb + e];
        splitf16_8(va, &hi, &lo);
        *(uint4*)(dsm + 64 * 128 + stsA0) = hi;
        *(uint4*)(dsm + 64 * 128 + stsA1) = lo;
        cvtf16_8(rb, &hi);
        *(uint4*)(dsm + UG_BH + rB * 256 + stsB) = hi;
        cvtf16_8(rb + 8, &hi);
        *(uint4*)(dsm + UG_BH + (rB + 16) * 256 + stsB) = hi;
    }
    {
        const float* pa = Sb + 32;
        const float* pb = Qb + (size_t)32 * DD;
        *(float4*)(ra) = *(const float4*)(pa);
        *(float4*)(ra + 4) = *(const float4*)(pa + 4);
        *(float4*)(ra + 8) = *(const float4*)(pa + (size_t)64 * JJ);
        *(float4*)(ra + 12) = *(const float4*)(pa + (size_t)64 * JJ + 4);
        *(float4*)(rb) = *(const float4*)(pb);
        *(float4*)(rb + 4) = *(const float4*)(pb + 4);
        *(float4*)(rb + 8) = *(const float4*)(pb + (size_t)16 * DD);
        *(float4*)(rb + 12) = *(const float4*)(pb + (size_t)16 * DD + 4);
    }
    __syncthreads();

    const int wm = wid >> 2, wn = wid & 3;
    float acc[4][4][4];
#pragma unroll
    for (int i = 0; i < 4; i++)
#pragma unroll
        for (int j = 0; j < 4; j++)
#pragma unroll
            for (int e = 0; e < 4; e++) acc[i][j][e] = 0.f;

    const int lsw = lane & 7;
    const int arow = wm * 64 + (lane & 7) + ((lane >> 3) & 1) * 8;
    const int ack = lane >> 4;
    const int bkrow = (lane & 7) + ((lane >> 3) & 1) * 8;
    const int bcn = wn * 4 + (lane >> 4);

#pragma unroll 1
    for (int kc = 0; kc < 8; kc++) {
        if (kc < 7) {
            char* st = dsm + ((kc + 1) & 1) * UG_STAGE;
            const int jb = (kc + 1) * 32 + sc * 8;
            float va[8];
            uint4 hi, lo;
#pragma unroll
            for (int e = 0; e < 8; e++) va[e] = __expf(ra[e] - Ms[jb + e]) * iZs[jb + e];
            splitf16_8(va, &hi, &lo);
            *(uint4*)(st + stsA0) = hi;
            *(uint4*)(st + stsA1) = lo;
#pragma unroll
            for (int e = 0; e < 8; e++) va[e] = __expf(ra[8 + e] - Ms[jb + e]) * iZs[jb + e];
            splitf16_8(va, &hi, &lo);
            *(uint4*)(st + 64 * 128 + stsA0) = hi;
            *(uint4*)(st + 64 * 128 + stsA1) = lo;
            cvtf16_8(rb, &hi);
            *(uint4*)(st + UG_BH + rB * 256 + stsB) = hi;
            cvtf16_8(rb + 8, &hi);
            *(uint4*)(st + UG_BH + (rB + 16) * 256 + stsB) = hi;
        }
        if (kc < 6) {
            const float* pa = Sb + (kc + 2) * 32;
            const float* pb = Qb + (size_t)(kc + 2) * 32 * DD;
            *(float4*)(ra) = *(const float4*)(pa);
            *(float4*)(ra + 4) = *(const float4*)(pa + 4);
            *(float4*)(ra + 8) = *(const float4*)(pa + (size_t)64 * JJ);
            *(float4*)(ra + 12) = *(const float4*)(pa + (size_t)64 * JJ + 4);
            *(float4*)(rb) = *(const float4*)(pb);
            *(float4*)(rb + 4) = *(const float4*)(pb + 4);
            *(float4*)(rb + 8) = *(const float4*)(pb + (size_t)16 * DD);
            *(float4*)(rb + 12) = *(const float4*)(pb + (size_t)16 * DD + 4);
        }
        const uint32_t sb = smb + (kc & 1) * UG_STAGE;
#pragma unroll
        for (int ks = 0; ks < 2; ks++) {
            uint32_t Ah[4][4], Al[4][4], Bf[2][4];
            const int ca = ks * 2 + ack;
            const int krow = ks * 16 + bkrow;
#pragma unroll
            for (int mi = 0; mi < 4; mi++) {
                uint32_t ro = (arow + mi * 16) * 128;
                ldmx4(Ah[mi], sb + ro + ((ca ^ lsw) << 4));
                ldmx4(Al[mi], sb + ro + (((ca + 4) ^ lsw) << 4));
            }
#pragma unroll
            for (int n2 = 0; n2 < 2; n2++) {
                const int cn = bcn + n2 * 2;
                const uint32_t co = ((((cn ^ lsw) & 7) | (cn & 8)) << 4);
                ldmx4t(Bf[n2], sb + UG_BH + krow * 256 + co);
            }
#pragma unroll
            for (int mi = 0; mi < 4; mi++)
#pragma unroll
                for (int ni = 0; ni < 4; ni++) {
                    const uint32_t* bp = &Bf[ni >> 1][(ni & 1) * 2];
                    mma_f16(acc[mi][ni], Ah[mi], bp[0], bp[1]);
                }
#pragma unroll
            for (int mi = 0; mi < 4; mi++)
#pragma unroll
                for (int ni = 0; ni < 4; ni++) {
                    const uint32_t* bp = &Bf[ni >> 1][(ni & 1) * 2];
                    mma_f16(acc[mi][ni], Al[mi], bp[0], bp[1]);
                }
        }
        __syncthreads();
    }

    // stage U in smem, then coalesced G epilogue
    float* st = (float*)dsm;
    const int g = lane >> 2, tc = (lane & 3) * 2;
#pragma unroll
    for (int mi = 0; mi < 4; mi++) {
        const int r0 = wm * 64 + mi * 16 + g;
#pragma unroll
        for (int ni = 0; ni < 4; ni++) {
            const int cl = wn * 32 + ni * 8 + tc;
            st[r0 * 128 + cl] = acc[mi][ni][0];
            st[r0 * 128 + cl + 1] = acc[mi][ni][1];
            st[(r0 + 8) * 128 + cl] = acc[mi][ni][2];
            st[(r0 + 8) * 128 + cl + 1] = acc[mi][ni][3];
        }
    }
    __syncthreads();
#pragma unroll
    for (int it = 0; it < 16; it++) {
        const int idx = it * 256 + tid;
        const int r = idx >> 5, c4 = (idx & 31) * 4;
        float4 u4 = *(float4*)&st[r * 128 + c4];
        float4 cv = *(const float4*)(C + ((size_t)(b * TT + t0 + r)) * DD + d0 + c4);
        float4 h4 = *(const float4*)&hs[c4];
        float* grow = G + ((size_t)(b * TT + t0 + r)) * (4 * DD);
        *(float4*)(grow + d0 + c4) = cv;
        *(float4*)(grow + DD + d0 + c4) = u4;
        *(float4*)(grow + 2 * DD + d0 + c4) =
            make_float4(cv.x * u4.x, cv.y * u4.y, cv.z * u4.z, cv.w * u4.w);
        *(float4*)(grow + 3 * DD + d0 + c4) =
            make_float4(cv.x * h4.x, cv.y * h4.y, cv.z * h4.z, cv.w * h4.w);
    }
}

// ---------------- launch ----------------------------------------------------
extern "C" void kernel_launch(void* const* d_in, const int* in_sizes, int n_in,
                              void* d_out, int out_size) {
    const float* C  = (const float*)d_in[0];
    const float* Q  = (const float*)d_in[1];
    const float* wa = (const float*)d_in[2];
    float* G = (float*)d_out;

    cudaFuncSetAttribute(k_s_mma, cudaFuncAttributeMaxDynamicSharedMemorySize, 2 * SG_STAGE);
    cudaFuncSetAttribute(k_u_mma, cudaFuncAttributeMaxDynamicSharedMemorySize, 65536);

    float* d_c1; cudaGetSymbolAddress((void**)&d_c1, g_c1);
    float* d_q2; cudaGetSymbolAddress((void**)&d_q2, g_q2);

    k_rowdot<<<(BB * TT) / 8, 256>>>(C, wa, d_c1, BB * TT);
    k_rowdot<<<(BB * JJ) / 8, 256>>>(Q, wa + DD, d_q2, BB * JJ);

    dim3 gs(JJ / 128, TT / 128, BB);
    k_s_mma<<<gs, 256, 2 * SG_STAGE>>>(C, Q, wa + 2 * DD);

    k_colcombine<<<BB, 256>>>();
    k_bt<<<BB, 256>>>();
    dim3 g2(NCHUNK, BB);
    k_hpart<<<g2, 256>>>(C);
    k_hcombine<<<BB, 512>>>();

    dim3 gu(DD / 128, TT / 128, BB);
    k_u_mma<<<gu, 256, 65536>>>(C, Q, G);
}

// round 7
// speedup vs baseline: 1.6070x; 1.3416x over previous
#include <cuda_runtime.h>
#include <cuda_bf16.h>
#include <cuda_fp16.h>
#include <math.h>
#include <stdint.h>

#define BB 32
#define TT 1024
#define JJ 256
#define DD 512
#define NCHUNK 8

// ---------------- scratch (device globals) ----------------------------------
__device__ float g_S[BB * TT * JJ];      // raw S (32 MB)
__device__ float g_c1[BB * TT];
__device__ float g_q2[BB * JJ];
__device__ float g_mp[BB * 2 * TT];      // row-max partials (per j-tile)
__device__ float g_pM[BB * NCHUNK * JJ];
__device__ float g_pZ[BB * NCHUNK * JJ];
__device__ float g_M[BB * JJ];
__device__ float g_invZ[BB * JJ];
__device__ float g_bt[BB * TT];
__device__ float g_hp[BB * NCHUNK * DD];
__device__ float g_h[BB * DD];

// ---------------- helpers ----------------------------------------------------
__device__ __forceinline__ uint32_t smem_u32(const void* p) {
    uint32_t a;
    asm("{ .reg .u64 t; cvta.to.shared.u64 t, %1; cvt.u32.u64 %0, t; }" : "=r"(a) : "l"(p));
    return a;
}
__device__ __forceinline__ void ldmx4(uint32_t* r, uint32_t a) {
    asm volatile("ldmatrix.sync.aligned.m8n8.x4.shared.b16 {%0,%1,%2,%3}, [%4];"
                 : "=r"(r[0]), "=r"(r[1]), "=r"(r[2]), "=r"(r[3]) : "r"(a));
}
__device__ __forceinline__ void ldmx4t(uint32_t* r, uint32_t a) {
    asm volatile("ldmatrix.sync.aligned.m8n8.x4.trans.shared.b16 {%0,%1,%2,%3}, [%4];"
                 : "=r"(r[0]), "=r"(r[1]), "=r"(r[2]), "=r"(r[3]) : "r"(a));
}
__device__ __forceinline__ void mma_f16(float* c, const uint32_t* a, uint32_t b0, uint32_t b1) {
    asm volatile(
        "mma.sync.aligned.m16n8k16.row.col.f32.f16.f16.f32 "
        "{%0,%1,%2,%3}, {%4,%5,%6,%7}, {%8,%9}, {%0,%1,%2,%3};"
        : "+f"(c[0]), "+f"(c[1]), "+f"(c[2]), "+f"(c[3])
        : "r"(a[0]), "r"(a[1]), "r"(a[2]), "r"(a[3]), "r"(b0), "r"(b1));
}
// fp16 convert 8 floats -> 16B
__device__ __forceinline__ void cvtf16_8(const float* v, uint4* hi) {
    uint32_t h[4];
#pragma unroll
    for (int p = 0; p < 4; p++)
        asm("cvt.rn.f16x2.f32 %0, %1, %2;" : "=r"(h[p]) : "f"(v[2 * p + 1]), "f"(v[2 * p]));
    *hi = make_uint4(h[0], h[1], h[2], h[3]);
}

// ---------------- K0: row dot products --------------------------------------
__global__ __launch_bounds__(256) void k_rowdot(const float* __restrict__ X,
                                                const float* __restrict__ w,
                                                float* __restrict__ out, int nrows) {
    int warp = (blockIdx.x * 256 + threadIdx.x) >> 5;
    int lane = threadIdx.x & 31;
    if (warp >= nrows) return;
    const float* row = X + (size_t)warp * DD;
    float s = 0.f;
#pragma unroll
    for (int i = 0; i < DD / 32; i++)
        s += row[lane + i * 32] * __ldg(&w[lane + i * 32]);
#pragma unroll
    for (int o = 16; o > 0; o >>= 1) s += __shfl_down_sync(0xffffffffu, s, o);
    if (lane == 0) out[warp] = s;
}

// ---------------- S-GEMM: S[128t x 128j] = (C.*w3)@Q^T + c1 + q2 -------------
// Stage: A (128 rows x 64B fp16) 8KB + B (128 rows x 64B fp16) 8KB = 16KB; x2.
#define SG_STAGE 16384
#define SG_B_OFF 8192
__global__ __launch_bounds__(256) void k_s_mma(const float* __restrict__ C,
                                               const float* __restrict__ Q,
                                               const float* __restrict__ w3) {
    extern __shared__ __align__(16) char dsm[];
    __shared__ float w3s[512];
    __shared__ float c1s[128], q2s[128];
    __shared__ float sRM[4][128];
    __shared__ float sCM[2][128], sCZ[2][128];

    const int tid = threadIdx.x, lane = tid & 31, wid = tid >> 5;
    const int b = blockIdx.z, tb = blockIdx.y, jt = blockIdx.x;
    const int t0 = tb * 128, j0 = jt * 128;

    w3s[tid] = w3[tid];
    w3s[tid + 256] = w3[tid + 256];
    if (tid < 128) {
        c1s[tid] = g_c1[b * TT + t0 + tid];
        q2s[tid] = g_q2[b * JJ + j0 + tid];
    }
    __syncthreads();

    const uint32_t smb = smem_u32(dsm);
    const int sr = tid >> 2, sc = tid & 3;
    const int ssw = (sr >> 1) & 3;        // invariant under +64
    const float* Ab = C + ((size_t)(b * TT + t0 + sr)) * DD + sc * 8;
    const float* Bb = Q + ((size_t)(b * JJ + j0 + sr)) * DD + sc * 8;
    const uint32_t stsA = sr * 64 + ((sc ^ ssw) << 4);
    const uint32_t stsB = SG_B_OFF + sr * 64 + ((sc ^ ssw) << 4);

    float ra[16], rb[16];
    // load chunk 0
    {
        *(float4*)(ra) = *(const float4*)(Ab);
        *(float4*)(ra + 4) = *(const float4*)(Ab + 4);
        *(float4*)(ra + 8) = *(const float4*)(Ab + (size_t)64 * DD);
        *(float4*)(ra + 12) = *(const float4*)(Ab + (size_t)64 * DD + 4);
        *(float4*)(rb) = *(const float4*)(Bb);
        *(float4*)(rb + 4) = *(const float4*)(Bb + 4);
        *(float4*)(rb + 8) = *(const float4*)(Bb + (size_t)64 * DD);
        *(float4*)(rb + 12) = *(const float4*)(Bb + (size_t)64 * DD + 4);
    }
    // convert chunk 0 -> stage 0
    {
        const float* w = &w3s[sc * 8];
        float va[8];
        uint4 hi;
#pragma unroll
        for (int e = 0; e < 8; e++) va[e] = ra[e] * w[e];
        cvtf16_8(va, &hi);
        *(uint4*)(dsm + stsA) = hi;
#pragma unroll
        for (int e = 0; e < 8; e++) va[e] = ra[8 + e] * w[e];
        cvtf16_8(va, &hi);
        *(uint4*)(dsm + stsA + 64 * 64) = hi;
        cvtf16_8(rb, &hi);
        *(uint4*)(dsm + stsB) = hi;
        cvtf16_8(rb + 8, &hi);
        *(uint4*)(dsm + stsB + 64 * 64) = hi;
    }
    // load chunk 1
    {
        const float* pa = Ab + 32;
        const float* pb = Bb + 32;
        *(float4*)(ra) = *(const float4*)(pa);
        *(float4*)(ra + 4) = *(const float4*)(pa + 4);
        *(float4*)(ra + 8) = *(const float4*)(pa + (size_t)64 * DD);
        *(float4*)(ra + 12) = *(const float4*)(pa + (size_t)64 * DD + 4);
        *(float4*)(rb) = *(const float4*)(pb);
        *(float4*)(rb + 4) = *(const float4*)(pb + 4);
        *(float4*)(rb + 8) = *(const float4*)(pb + (size_t)64 * DD);
        *(float4*)(rb + 12) = *(const float4*)(pb + (size_t)64 * DD + 4);
    }
    __syncthreads();

    const int wm = wid >> 2, wn = wid & 3;
    float acc[4][4][4];
#pragma unroll
    for (int i = 0; i < 4; i++)
#pragma unroll
        for (int j = 0; j < 4; j++)
#pragma unroll
            for (int e = 0; e < 4; e++) acc[i][j][e] = 0.f;

    const int arow = wm * 64 + (lane & 7) + ((lane >> 3) & 1) * 8;
    const int aswz = (arow >> 1) & 3;     // invariant under +16
    const int ack = lane >> 4;
    const int bj = wn * 32 + (lane & 7) + ((lane >> 4) & 1) * 8;
    const int bsw3 = (bj >> 1) & 3;       // invariant under +16
    const int bck = (lane >> 3) & 1;

#pragma unroll 1
    for (int kc = 0; kc < 16; kc++) {
        // convert chunk kc+1 into next stage (overlaps with this chunk's MMA issue)
        if (kc < 15) {
            char* st = dsm + ((kc + 1) & 1) * SG_STAGE;
            const float* w = &w3s[(kc + 1) * 32 + sc * 8];
            float va[8];
            uint4 hi;
#pragma unroll
            for (int e = 0; e < 8; e++) va[e] = ra[e] * w[e];
            cvtf16_8(va, &hi);
            *(uint4*)(st + stsA) = hi;
#pragma unroll
            for (int e = 0; e < 8; e++) va[e] = ra[8 + e] * w[e];
            cvtf16_8(va, &hi);
            *(uint4*)(st + stsA + 64 * 64) = hi;
            cvtf16_8(rb, &hi);
            *(uint4*)(st + stsB) = hi;
            cvtf16_8(rb + 8, &hi);
            *(uint4*)(st + stsB + 64 * 64) = hi;
        }
        if (kc < 14) {
            const float* pa = Ab + (kc + 2) * 32;
            const float* pb = Bb + (kc + 2) * 32;
            *(float4*)(ra) = *(const float4*)(pa);
            *(float4*)(ra + 4) = *(const float4*)(pa + 4);
            *(float4*)(ra + 8) = *(const float4*)(pa + (size_t)64 * DD);
            *(float4*)(ra + 12) = *(const float4*)(pa + (size_t)64 * DD + 4);
            *(float4*)(rb) = *(const float4*)(pb);
            *(float4*)(rb + 4) = *(const float4*)(pb + 4);
            *(float4*)(rb + 8) = *(const float4*)(pb + (size_t)64 * DD);
            *(float4*)(rb + 12) = *(const float4*)(pb + (size_t)64 * DD + 4);
        }
        const uint32_t sb = smb + (kc & 1) * SG_STAGE;
#pragma unroll
        for (int ks = 0; ks < 2; ks++) {
            uint32_t Af[4][4], Bf[2][4];
            const int ca = ks * 2 + ack;
            const int cb = ks * 2 + bck;
#pragma unroll
            for (int mi = 0; mi < 4; mi++)
                ldmx4(Af[mi], sb + (uint32_t)(arow + mi * 16) * 64 + ((ca ^ aswz) << 4));
#pragma unroll
            for (int n2 = 0; n2 < 2; n2++)
                ldmx4(Bf[n2], sb + SG_B_OFF + (uint32_t)(bj + n2 * 16) * 64 + ((cb ^ bsw3) << 4));
#pragma unroll
            for (int mi = 0; mi < 4; mi++)
#pragma unroll
                for (int ni = 0; ni < 4; ni++) {
                    const uint32_t* bp = &Bf[ni >> 1][(ni & 1) * 2];
                    mma_f16(acc[mi][ni], Af[mi], bp[0], bp[1]);
                }
        }
        __syncthreads();
    }

    // ---- epilogue: biases, store S, fused row-max + column partial stats ----
    const int g = lane >> 2, tc = (lane & 3) * 2;
#pragma unroll
    for (int mi = 0; mi < 4; mi++) {
        const int tl = wm * 64 + mi * 16 + g;
        const float c1a = c1s[tl], c1b = c1s[tl + 8];
        float* row0 = &g_S[((size_t)(b * TT + t0 + tl)) * JJ + j0];
        float* row1 = row0 + (size_t)8 * JJ;
#pragma unroll
        for (int ni = 0; ni < 4; ni++) {
            const int jl = wn * 32 + ni * 8 + tc;
            const float q2a = q2s[jl], q2b = q2s[jl + 1];
            acc[mi][ni][0] += c1a + q2a;
            acc[mi][ni][1] += c1a + q2b;
            acc[mi][ni][2] += c1b + q2a;
            acc[mi][ni][3] += c1b + q2b;
            *(float2*)(row0 + jl) = make_float2(acc[mi][ni][0], acc[mi][ni][1]);
            *(float2*)(row1 + jl) = make_float2(acc[mi][ni][2], acc[mi][ni][3]);
        }
    }
    // row max over this CTA's 128 j
#pragma unroll
    for (int mi = 0; mi < 4; mi++) {
#pragma unroll
        for (int rr = 0; rr < 2; rr++) {
            float m = -1e30f;
#pragma unroll
            for (int ni = 0; ni < 4; ni++)
                m = fmaxf(m, fmaxf(acc[mi][ni][rr * 2], acc[mi][ni][rr * 2 + 1]));
            m = fmaxf(m, __shfl_xor_sync(0xffffffffu, m, 1));
            m = fmaxf(m, __shfl_xor_sync(0xffffffffu, m, 2));
            if ((lane & 3) == 0) sRM[wn][wm * 64 + mi * 16 + g + rr * 8] = m;
        }
    }
    // column stats (max & sum-exp over this CTA's 128 t)
#pragma unroll
    for (int ni = 0; ni < 4; ni++) {
#pragma unroll
        for (int cc = 0; cc < 2; cc++) {
            float m = -1e30f;
#pragma unroll
            for (int mi = 0; mi < 4; mi++)
                m = fmaxf(m, fmaxf(acc[mi][ni][cc], acc[mi][ni][2 + cc]));
            float z = 0.f;
#pragma unroll
            for (int mi = 0; mi < 4; mi++)
                z += __expf(acc[mi][ni][cc] - m) + __expf(acc[mi][ni][2 + cc] - m);
#pragma unroll
            for (int o = 4; o < 32; o <<= 1) {
                float Mo = __shfl_xor_sync(0xffffffffu, m, o);
                float Zo = __shfl_xor_sync(0xffffffffu, z, o);
                float nm = fmaxf(m, Mo);
                z = z * __expf(m - nm) + Zo * __expf(Mo - nm);
                m = nm;
            }
            if (g == 0) {
                sCM[wm][wn * 32 + ni * 8 + tc + cc] = m;
                sCZ[wm][wn * 32 + ni * 8 + tc + cc] = z;
            }
        }
    }
    __syncthreads();
    if (tid < 128) {
        float m = fmaxf(fmaxf(sRM[0][tid], sRM[1][tid]), fmaxf(sRM[2][tid], sRM[3][tid]));
        g_mp[((size_t)(b * 2 + jt)) * TT + t0 + tid] = m;
        float M0 = sCM[0][tid], M1 = sCM[1][tid];
        float nm = fmaxf(M0, M1);
        float Z = sCZ[0][tid] * __expf(M0 - nm) + sCZ[1][tid] * __expf(M1 - nm);
        g_pM[(b * NCHUNK + tb) * JJ + j0 + tid] = nm;
        g_pZ[(b * NCHUNK + tb) * JJ + j0 + tid] = Z;
    }
}

// ---------------- combine / bt / h -------------------------------------------
__global__ __launch_bounds__(256) void k_colcombine() {
    int b = blockIdx.x, j = threadIdx.x;
    float M = -1e30f;
#pragma unroll
    for (int c = 0; c < NCHUNK; c++) M = fmaxf(M, g_pM[(b * NCHUNK + c) * JJ + j]);
    float Z = 0.f;
#pragma unroll
    for (int c = 0; c < NCHUNK; c++)
        Z += g_pZ[(b * NCHUNK + c) * JJ + j] * __expf(g_pM[(b * NCHUNK + c) * JJ + j] - M);
    g_M[b * JJ + j] = M;
    g_invZ[b * JJ + j] = 1.0f / Z;
}
__global__ __launch_bounds__(256) void k_bt() {
    __shared__ float red[256];
    int b = blockIdx.x, tid = threadIdx.x;
    float mv[4];
#pragma unroll
    for (int i = 0; i < 4; i++) {
        int t = tid + i * 256;
        mv[i] = fmaxf(g_mp[((size_t)(b * 2)) * TT + t], g_mp[((size_t)(b * 2 + 1)) * TT + t]);
    }
    float mx = fmaxf(fmaxf(mv[0], mv[1]), fmaxf(mv[2], mv[3]));
    red[tid] = mx;
    __syncthreads();
    for (int s = 128; s > 0; s >>= 1) {
        if (tid < s) red[tid] = fmaxf(red[tid], red[tid + s]);
        __syncthreads();
    }
    float bmax = red[0];
    __syncthreads();
    float e[4], ssum = 0.f;
#pragma unroll
    for (int i = 0; i < 4; i++) { e[i] = __expf(mv[i] - bmax); ssum += e[i]; }
    red[tid] = ssum;
    __syncthreads();
    for (int s = 128; s > 0; s >>= 1) {
        if (tid < s) red[tid] += red[tid + s];
        __syncthreads();
    }
    float inv = 1.0f / red[0];
#pragma unroll
    for (int i = 0; i < 4; i++) g_bt[b * TT + tid + i * 256] = e[i] * inv;
}
__global__ __launch_bounds__(256) void k_hpart(const float* __restrict__ C) {
    __shared__ float bts[TT / NCHUNK];
    int b = blockIdx.y, chunk = blockIdx.x;
    int tid = threadIdx.x;
    if (tid < TT / NCHUNK) bts[tid] = g_bt[b * TT + chunk * (TT / NCHUNK) + tid];
    __syncthreads();
    float a0 = 0.f, a1 = 0.f;
    for (int tt = 0; tt < TT / NCHUNK; tt++) {
        int t = chunk * (TT / NCHUNK) + tt;
        const float* cr = C + ((size_t)(b * TT + t)) * DD;
        a0 = fmaf(bts[tt], cr[tid], a0);
        a1 = fmaf(bts[tt], cr[tid + 256], a1);
    }
    g_hp[(b * NCHUNK + chunk) * DD + tid] = a0;
    g_hp[(b * NCHUNK + chunk) * DD + tid + 256] = a1;
}
__global__ __launch_bounds__(512) void k_hcombine() {
    int b = blockIdx.x, d = threadIdx.x;
    float s = 0.f;
#pragma unroll
    for (int c = 0; c < NCHUNK; c++) s += g_hp[(b * NCHUNK + c) * DD + d];
    g_h[b * DD + d] = s;
}

// ---------------- U-GEMM: U[128t x 128d] = softmax(S) @ Q, full G epilogue ---
// Stage: A (128 rows x 64B fp16) 8KB + B (32 k-rows x 256B fp16) 8KB = 16KB; x2.
#define UG_STAGE 16384
#define UG_BH 8192
__global__ __launch_bounds__(256) void k_u_mma(const float* __restrict__ C,
                                               const float* __restrict__ Q,
                                               float* __restrict__ G) {
    extern __shared__ __align__(16) char dsm[];
    __shared__ float Ms[256], iZs[256], hs[128];

    const int tid = threadIdx.x, lane = tid & 31, wid = tid >> 5;
    const int b = blockIdx.z, t0 = blockIdx.y * 128, d0 = blockIdx.x * 128;

    Ms[tid] = g_M[b * JJ + tid];
    iZs[tid] = g_invZ[b * JJ + tid];
    if (tid < 128) hs[tid] = g_h[b * DD + d0 + tid];
    __syncthreads();

    const uint32_t smb = smem_u32(dsm);
    const int sr = tid >> 2, sc = tid & 3;
    const int ssw = (sr >> 1) & 3;
    const int rB = tid >> 4, cB = tid & 15;
    const int bsw = rB & 7;
    const float* Sb = g_S + ((size_t)(b * TT + t0 + sr)) * JJ + sc * 8;
    const float* Qb = Q + ((size_t)(b * JJ + rB)) * DD + d0 + cB * 8;
    const uint32_t stsA = sr * 64 + ((sc ^ ssw) << 4);
    const uint32_t stsB = (((cB ^ bsw) & 7) | (cB & 8)) << 4;

    float ra[16], rb[16];
    {
        *(float4*)(ra) = *(const float4*)(Sb);
        *(float4*)(ra + 4) = *(const float4*)(Sb + 4);
        *(float4*)(ra + 8) = *(const float4*)(Sb + (size_t)64 * JJ);
        *(float4*)(ra + 12) = *(const float4*)(Sb + (size_t)64 * JJ + 4);
        *(float4*)(rb) = *(const float4*)(Qb);
        *(float4*)(rb + 4) = *(const float4*)(Qb + 4);
        *(float4*)(rb + 8) = *(const float4*)(Qb + (size_t)16 * DD);
        *(float4*)(rb + 12) = *(const float4*)(Qb + (size_t)16 * DD + 4);
    }
    {
        const int jb = sc * 8;
        float va[8];
        uint4 hi;
#pragma unroll
        for (int e = 0; e < 8; e++) va[e] = __expf(ra[e] - Ms[jb + e]) * iZs[jb + e];
        cvtf16_8(va, &hi);
        *(uint4*)(dsm + stsA) = hi;
#pragma unroll
        for (int e = 0; e < 8; e++) va[e] = __expf(ra[8 + e] - Ms[jb + e]) * iZs[jb + e];
        cvtf16_8(va, &hi);
        *(uint4*)(dsm + stsA + 64 * 64) = hi;
        cvtf16_8(rb, &hi);
        *(uint4*)(dsm + UG_BH + rB * 256 + stsB) = hi;
        cvtf16_8(rb + 8, &hi);
        *(uint4*)(dsm + UG_BH + (rB + 16) * 256 + stsB) = hi;
    }
    {
        const float* pa = Sb + 32;
        const float* pb = Qb + (size_t)32 * DD;
        *(float4*)(ra) = *(const float4*)(pa);
        *(float4*)(ra + 4) = *(const float4*)(pa + 4);
        *(float4*)(ra + 8) = *(const float4*)(pa + (size_t)64 * JJ);
        *(float4*)(ra + 12) = *(const float4*)(pa + (size_t)64 * JJ + 4);
        *(float4*)(rb) = *(const float4*)(pb);
        *(float4*)(rb + 4) = *(const float4*)(pb + 4);
        *(float4*)(rb + 8) = *(const float4*)(pb + (size_t)16 * DD);
        *(float4*)(rb + 12) = *(const float4*)(pb + (size_t)16 * DD + 4);
    }
    __syncthreads();

    const int wm = wid >> 2, wn = wid & 3;
    float acc[4][4][4];
#pragma unroll
    for (int i = 0; i < 4; i++)
#pragma unroll
        for (int j = 0; j < 4; j++)
#pragma unroll
            for (int e = 0; e < 4; e++) acc[i][j][e] = 0.f;

    const int lsw = lane & 7;
    const int arow = wm * 64 + (lane & 7) + ((lane >> 3) & 1) * 8;
    const int aswz = (arow >> 1) & 3;
    const int ack = lane >> 4;
    const int bkrow = (lane & 7) + ((lane >> 3) & 1) * 8;
    const int bcn = wn * 4 + (lane >> 4);

#pragma unroll 1
    for (int kc = 0; kc < 8; kc++) {
        if (kc < 7) {
            char* st = dsm + ((kc + 1) & 1) * UG_STAGE;
            const int jb = (kc + 1) * 32 + sc * 8;
            float va[8];
            uint4 hi;
#pragma unroll
            for (int e = 0; e < 8; e++) va[e] = __expf(ra[e] - Ms[jb + e]) * iZs[jb + e];
            cvtf16_8(va, &hi);
            *(uint4*)(st + stsA) = hi;
#pragma unroll
            for (int e = 0; e < 8; e++) va[e] = __expf(ra[8 + e] - Ms[jb + e]) * iZs[jb + e];
            cvtf16_8(va, &hi);
            *(uint4*)(st + stsA + 64 * 64) = hi;
            cvtf16_8(rb, &hi);
            *(uint4*)(st + UG_BH + rB * 256 + stsB) = hi;
            cvtf16_8(rb + 8, &hi);
            *(uint4*)(st + UG_BH + (rB + 16) * 256 + stsB) = hi;
        }
        if (kc < 6) {
            const float* pa = Sb + (kc + 2) * 32;
            const float* pb = Qb + (size_t)(kc + 2) * 32 * DD;
            *(float4*)(ra) = *(const float4*)(pa);
            *(float4*)(ra + 4) = *(const float4*)(pa + 4);
            *(float4*)(ra + 8) = *(const float4*)(pa + (size_t)64 * JJ);
            *(float4*)(ra + 12) = *(const float4*)(pa + (size_t)64 * JJ + 4);
            *(float4*)(rb) = *(const float4*)(pb);
            *(float4*)(rb + 4) = *(const float4*)(pb + 4);
            *(float4*)(rb + 8) = *(const float4*)(pb + (size_t)16 * DD);
            *(float4*)(rb + 12) = *(const float4*)(pb + (size_t)16 * DD + 4);
        }
        const uint32_t sb = smb + (kc & 1) * UG_STAGE;
#pragma unroll
        for (int ks = 0; ks < 2; ks++) {
            uint32_t Af[4][4], Bf[2][4];
            const int ca = ks * 2 + ack;
            const int krow = ks * 16 + bkrow;
#pragma unroll
            for (int mi = 0; mi < 4; mi++)
                ldmx4(Af[mi], sb + (uint32_t)(arow + mi * 16) * 64 + ((ca ^ aswz) << 4));
#pragma unroll
            for (int n2 = 0; n2 < 2; n2++) {
                const int cn = bcn + n2 * 2;
                const uint32_t co = ((((cn ^ lsw) & 7) | (cn & 8)) << 4);
                ldmx4t(Bf[n2], sb + UG_BH + krow * 256 + co);
            }
#pragma unroll
            for (int mi = 0; mi < 4; mi++)
#pragma unroll
                for (int ni = 0; ni < 4; ni++) {
                    const uint32_t* bp = &Bf[ni >> 1][(ni & 1) * 2];
                    mma_f16(acc[mi][ni], Af[mi], bp[0], bp[1]);
                }
        }
        __syncthreads();
    }

    // stage U in smem, then coalesced G epilogue
    float* st = (float*)dsm;
    const int g = lane >> 2, tc = (lane & 3) * 2;
#pragma unroll
    for (int mi = 0; mi < 4; mi++) {
        const int r0 = wm * 64 + mi * 16 + g;
#pragma unroll
        for (int ni = 0; ni < 4; ni++) {
            const int cl = wn * 32 + ni * 8 + tc;
            st[r0 * 128 + cl] = acc[mi][ni][0];
            st[r0 * 128 + cl + 1] = acc[mi][ni][1];
            st[(r0 + 8) * 128 + cl] = acc[mi][ni][2];
            st[(r0 + 8) * 128 + cl + 1] = acc[mi][ni][3];
        }
    }
    __syncthreads();
#pragma unroll
    for (int it = 0; it < 16; it++) {
        const int idx = it * 256 + tid;
        const int r = idx >> 5, c4 = (idx & 31) * 4;
        float4 u4 = *(float4*)&st[r * 128 + c4];
        float4 cv = *(const float4*)(C + ((size_t)(b * TT + t0 + r)) * DD + d0 + c4);
        float4 h4 = *(const float4*)&hs[c4];
        float* grow = G + ((size_t)(b * TT + t0 + r)) * (4 * DD);
        *(float4*)(grow + d0 + c4) = cv;
        *(float4*)(grow + DD + d0 + c4) = u4;
        *(float4*)(grow + 2 * DD + d0 + c4) =
            make_float4(cv.x * u4.x, cv.y * u4.y, cv.z * u4.z, cv.w * u4.w);
        *(float4*)(grow + 3 * DD + d0 + c4) =
            make_float4(cv.x * h4.x, cv.y * h4.y, cv.z * h4.z, cv.w * h4.w);
    }
}

// ---------------- launch ----------------------------------------------------
extern "C" void kernel_launch(void* const* d_in, const int* in_sizes, int n_in,
                              void* d_out, int out_size) {
    const float* C  = (const float*)d_in[0];
    const float* Q  = (const float*)d_in[1];
    const float* wa = (const float*)d_in[2];
    float* G = (float*)d_out;

    cudaFuncSetAttribute(k_s_mma, cudaFuncAttributeMaxDynamicSharedMemorySize, 2 * SG_STAGE);
    cudaFuncSetAttribute(k_u_mma, cudaFuncAttributeMaxDynamicSharedMemorySize, 65536);

    float* d_c1; cudaGetSymbolAddress((void**)&d_c1, g_c1);
    float* d_q2; cudaGetSymbolAddress((void**)&d_q2, g_q2);

    k_rowdot<<<(BB * TT) / 8, 256>>>(C, wa, d_c1, BB * TT);
    k_rowdot<<<(BB * JJ) / 8, 256>>>(Q, wa + DD, d_q2, BB * JJ);

    dim3 gs(JJ / 128, TT / 128, BB);
    k_s_mma<<<gs, 256, 2 * SG_STAGE>>>(C, Q, wa + 2 * DD);

    k_colcombine<<<BB, 256>>>();
    k_bt<<<BB, 256>>>();
    dim3 g2(NCHUNK, BB);
    k_hpart<<<g2, 256>>>(C);
    k_hcombine<<<BB, 512>>>();

    dim3 gu(DD / 128, TT / 128, BB);
    k_u_mma<<<gu, 256, 65536>>>(C, Q, G);
}